// round 8
// baseline (speedup 1.0000x reference)
#include <cuda_runtime.h>
#include <cuda_fp16.h>
#include <math.h>
#include <stdint.h>

#define NE   1024
#define NH   16
#define NKV  4
#define HD   64
#define SMAX 2048
#define BMAX 2
#define MMAX (BMAX*SMAX)
#define RMS_EPS 1.1920929e-07f
#define SM_SHIFT 13.0f

// ---------------- scratch (device globals; no allocation allowed) ----------
__device__ __half g_x[(size_t)MMAX*NE];          // x fp16
__device__ __half g_w[1536*1024];                // fused Wq|Wk|Wv fp16
__device__ __half g_wp[1024*1024];               // Wproj fp16
__device__ __half g_y[(size_t)MMAX*NE];          // attention out fp16
__device__ __half g_q[(size_t)BMAX*NH*SMAX*HD];  // roped q (scale+log2e folded)
__device__ __half g_k[(size_t)BMAX*NKV*SMAX*HD];
__device__ __half g_v[(size_t)BMAX*NKV*SMAX*HD];

// ---------------- PTX helpers (family-generic only) -------------------------
__device__ __forceinline__ uint32_t smem_to_u32(const void* p) {
    uint32_t a;
    asm("{ .reg .u64 t; cvta.to.shared.u64 t, %1; cvt.u32.u64 %0, t; }" : "=r"(a) : "l"(p));
    return a;
}
__device__ __forceinline__ void ldsm_x4(uint32_t& r0, uint32_t& r1, uint32_t& r2,
                                        uint32_t& r3, uint32_t addr) {
    asm volatile("ldmatrix.sync.aligned.m8n8.x4.shared.b16 {%0,%1,%2,%3}, [%4];"
        : "=r"(r0), "=r"(r1), "=r"(r2), "=r"(r3) : "r"(addr));
}
__device__ __forceinline__ void ldsm_x4_t(uint32_t& r0, uint32_t& r1, uint32_t& r2,
                                          uint32_t& r3, uint32_t addr) {
    asm volatile("ldmatrix.sync.aligned.m8n8.x4.trans.shared.b16 {%0,%1,%2,%3}, [%4];"
        : "=r"(r0), "=r"(r1), "=r"(r2), "=r"(r3) : "r"(addr));
}
__device__ __forceinline__ void mma_f16(float* c, const uint32_t* a, const uint32_t* b) {
    asm volatile("mma.sync.aligned.m16n8k16.row.col.f32.f16.f16.f32 "
        "{%0,%1,%2,%3}, {%4,%5,%6,%7}, {%8,%9}, {%0,%1,%2,%3};"
        : "+f"(c[0]), "+f"(c[1]), "+f"(c[2]), "+f"(c[3])
        : "r"(a[0]), "r"(a[1]), "r"(a[2]), "r"(a[3]), "r"(b[0]), "r"(b[1]));
}
__device__ __forceinline__ void cp16(uint32_t dst, const void* src) {
    asm volatile("cp.async.cg.shared.global [%0], [%1], 16;" :: "r"(dst), "l"(src));
}
#define CP_COMMIT() asm volatile("cp.async.commit_group;" ::: "memory")
#define CP_WAIT(n)  asm volatile("cp.async.wait_group %0;" :: "n"(n) : "memory")

__device__ __forceinline__ uint32_t pack_h2(float x, float y) {
    __half2 h = __floats2half2_rn(x, y);
    return *(uint32_t*)&h;
}
__device__ __forceinline__ float ex2(float x) {
    float r; asm("ex2.approx.ftz.f32 %0, %1;" : "=f"(r) : "f"(x)); return r;
}

// ---------------- merged fp32 -> fp16 convert --------------------------------
__global__ void __launch_bounds__(256) cvt_all(
    const float* __restrict__ x,  const float* __restrict__ Wq,
    const float* __restrict__ Wk, const float* __restrict__ Wv,
    const float* __restrict__ Wproj, __half* __restrict__ xo, int nx4)
{
    int i = blockIdx.x * 256 + threadIdx.x;
    const float* src;
    __half* h;
    int o;
    if (i < nx4) { src = x; h = xo; o = i; }
    else {
        i -= nx4;
        if      (i < 262144)  { src = Wq;    h = g_w;           o = i; }
        else if (i < 327680)  { src = Wk;    h = g_w + 1048576; o = i - 262144; }
        else if (i < 393216)  { src = Wv;    h = g_w + 1310720; o = i - 327680; }
        else if (i < 655360)  { src = Wproj; h = g_wp;          o = i - 393216; }
        else return;
    }
    float4 v = ((const float4*)src)[o];
    ((uint32_t*)h)[o*2]   = pack_h2(v.x, v.y);
    ((uint32_t*)h)[o*2+1] = pack_h2(v.z, v.w);
}

// ---------------- fp16 mma.sync GEMM: CTA 128x64, warp 16x64, 3 CTA/SM -------
#define STG_BYTES 24576   /* A (16KB) | B (8KB) */
#define GSMEM (3*STG_BYTES)

__device__ __forceinline__ void gemm_issue_stage(
    uint32_t sbase, int stg, int kc,
    const __half* __restrict__ A, const __half* __restrict__ W,
    int bm, int bn, int K, int tid)
{
    #pragma unroll
    for (int i = 0; i < 6; i++) {
        const int idx = i * 256 + tid;           // 0..1535
        const bool isB = idx >= 1024;
        const int cid = isB ? idx - 1024 : idx;
        const int row = cid >> 3, c16 = cid & 7;
        const uint32_t off = row * 128 + c16 * 16;
        const uint32_t sw = off ^ ((off >> 3) & 0x70);
        const int gk = kc * 64 + c16 * 8;
        const __half* src = isB ? (W + (size_t)(bn + row) * K + gk)
                                : (A + (size_t)(bm + row) * K + gk);
        cp16(sbase + stg * STG_BYTES + (isB ? 16384 : 0) + sw, src);
    }
}

// warp tile 16x64: c[8][4], one A ldsm + 4 B ldsm + 8 MMA per k16 step
__device__ __forceinline__ void gemm_mainloop(
    float c[8][4], uint32_t sbase,
    const __half* A, const __half* W, int bm, int bn, int tid)
{
    constexpr int K = 1024;
    constexpr int NK = K / 64;
    const int wid = tid >> 5, lane = tid & 31;
    const int rIn = lane & 7, mId = lane >> 3;

    #pragma unroll
    for (int n = 0; n < 8; n++)
        #pragma unroll
        for (int j = 0; j < 4; j++) c[n][j] = 0.f;

    gemm_issue_stage(sbase, 0, 0, A, W, bm, bn, K, tid); CP_COMMIT();
    gemm_issue_stage(sbase, 1, 1, A, W, bm, bn, K, tid); CP_COMMIT();

    for (int kc = 0; kc < NK; kc++) {
        const int stg = kc % 3;
        if (kc + 2 < NK) {
            gemm_issue_stage(sbase, (kc + 2) % 3, kc + 2, A, W, bm, bn, K, tid);
            CP_COMMIT();
            CP_WAIT(2);
        } else if (kc + 1 < NK) {
            CP_WAIT(1);
        } else {
            CP_WAIT(0);
        }
        __syncthreads();

        const uint32_t aA = sbase + stg * STG_BYTES;
        const uint32_t aB = aA + 16384;

        #pragma unroll
        for (int kk = 0; kk < 64; kk += 16) {
            uint32_t a[4];
            {
                const int row = wid * 16 + (mId & 1) * 8 + rIn;
                const int colB = (kk + (mId >> 1) * 8) * 2;
                const uint32_t off = row * 128 + colB;
                const uint32_t sw = off ^ ((off >> 3) & 0x70);
                ldsm_x4(a[0], a[1], a[2], a[3], aA + sw);
            }
            uint32_t b[8][2];
            #pragma unroll
            for (int nt = 0; nt < 4; nt++) {
                const int row = nt * 16 + (mId >> 1) * 8 + rIn;
                const int colB = (kk + (mId & 1) * 8) * 2;
                const uint32_t off = row * 128 + colB;
                const uint32_t sw = off ^ ((off >> 3) & 0x70);
                ldsm_x4(b[2*nt][0], b[2*nt][1], b[2*nt+1][0], b[2*nt+1][1], aB + sw);
            }
            #pragma unroll
            for (int n = 0; n < 8; n++)
                mma_f16(c[n], a, b[n]);
        }
        __syncthreads();
    }
}

// ---------------- proj GEMM (fp32 out) ---------------------------------------
__global__ void __launch_bounds__(256, 3) gemm_mma(
    const __half* __restrict__ A, const __half* __restrict__ W,
    float* __restrict__ C, int ldc)
{
    extern __shared__ char gsm[];
    const uint32_t sbase = smem_to_u32(gsm);
    const int tid = threadIdx.x, wid = tid >> 5, lane = tid & 31;
    const int bm = blockIdx.y * 128, bn = blockIdx.x * 64;

    float c[8][4];
    gemm_mainloop(c, sbase, A, W, bm, bn, tid);

    const int g = lane >> 2, t = lane & 3;
    #pragma unroll
    for (int n = 0; n < 8; n++) {
        const int r0 = bm + wid * 16 + g;
        const int col = bn + n * 8 + t * 2;
        *(float2*)&C[(size_t)r0 * ldc + col]       = make_float2(c[n][0], c[n][1]);
        *(float2*)&C[(size_t)(r0 + 8) * ldc + col] = make_float2(c[n][2], c[n][3]);
    }
}

// ---------------- QKV GEMM with fused rope/rmsnorm/gate epilogue -------------
// warp = 16 rows x the CTA's single 64-col head chunk.
__global__ void __launch_bounds__(256, 3) gemm_qkv(
    const __half* __restrict__ A, const __half* __restrict__ W,
    const float* __restrict__ x, const float* __restrict__ ve,
    const float* __restrict__ cosb, const float* __restrict__ sinb,
    const float* __restrict__ Wgate, int S)
{
    extern __shared__ char gsm[];
    const uint32_t sbase = smem_to_u32(gsm);
    const int tid = threadIdx.x, wid = tid >> 5, lane = tid & 31;
    const int bm = blockIdx.y * 128, bn = blockIdx.x * 64;

    float c[8][4];
    gemm_mainloop(c, sbase, A, W, bm, bn, tid);

    const int g = lane >> 2, t = lane & 3;
    const int colbase = bn;
    const int type = (colbase < 1024) ? 0 : (colbase < 1280 ? 1 : 2);
    const float sQK = (type == 0) ? (1.2f * 0.125f * 1.44269504f) : 1.2f;

    #pragma unroll
    for (int e = 0; e < 2; e++) {
        const int row = wid * 16 + g + e * 8;
        const int m = bm + row;
        const int b = m / S, s = m - b * S;
        if (type <= 1) {
            float r1[4][2], r2[4][2];
            float ss = 0.f;
            #pragma unroll
            for (int n = 0; n < 4; n++) {
                const int d0 = n * 8 + 2 * t;
                const float cs0 = cosb[s*32 + d0], cs1 = cosb[s*32 + d0 + 1];
                const float sn0 = sinb[s*32 + d0], sn1 = sinb[s*32 + d0 + 1];
                const float t1a = c[n][2*e],   t1b = c[n][2*e+1];
                const float t2a = c[n+4][2*e], t2b = c[n+4][2*e+1];
                r1[n][0] = t1a*cs0 + t2a*sn0;  r1[n][1] = t1b*cs1 + t2b*sn1;
                r2[n][0] = t2a*cs0 - t1a*sn0;  r2[n][1] = t2b*cs1 - t1b*sn1;
                ss += r1[n][0]*r1[n][0] + r1[n][1]*r1[n][1]
                    + r2[n][0]*r2[n][0] + r2[n][1]*r2[n][1];
            }
            ss += __shfl_xor_sync(0xffffffffu, ss, 1);
            ss += __shfl_xor_sync(0xffffffffu, ss, 2);
            const float inv = rsqrtf(ss * (1.0f/64.0f) + RMS_EPS) * sQK;
            __half* dst;
            size_t doff;
            if (type == 0) {
                const int hh = colbase >> 6;
                doff = ((size_t)(b*NH + hh)*S + s) * HD;
                dst = g_q;
            } else {
                const int kh = (colbase - 1024) >> 6;
                doff = ((size_t)(b*NKV + kh)*S + s) * HD;
                dst = g_k;
            }
            #pragma unroll
            for (int n = 0; n < 4; n++) {
                const int d0 = n * 8 + 2 * t;
                *(uint32_t*)(dst + doff + d0)      = pack_h2(r1[n][0]*inv, r1[n][1]*inv);
                *(uint32_t*)(dst + doff + d0 + 32) = pack_h2(r2[n][0]*inv, r2[n][1]*inv);
            }
        } else {
            const int kvh = (colbase - 1280) >> 6;
            float gz = 0.f;
            #pragma unroll
            for (int j = 0; j < 3; j++)
                gz += x[(size_t)m*NE + 3*t + j] * Wgate[kvh*12 + 3*t + j];
            gz += __shfl_xor_sync(0xffffffffu, gz, 1);
            gz += __shfl_xor_sync(0xffffffffu, gz, 2);
            const float gate = 3.0f / (1.0f + __expf(-gz));
            const size_t doff = ((size_t)(b*NKV + kvh)*S + s) * HD;
            const float* vep = ve + (size_t)m*256 + kvh*64;
            #pragma unroll
            for (int n = 0; n < 8; n++) {
                const int d0 = n * 8 + 2 * t;
                const float v0 = c[n][2*e]   + gate * vep[d0];
                const float v1 = c[n][2*e+1] + gate * vep[d0+1];
                *(uint32_t*)(g_v + doff + d0) = pack_h2(v0, v1);
            }
        }
    }
}

// ---------------- flash attention, fixed-shift softmax -----------------------
#define AOFF_Q   0
#define AOFF_STG 8192
#define ASTG_STRIDE 16640   /* K (8KB) + V (8KB) + amask (256B) */
#define ASMEM (AOFF_STG + 2*ASTG_STRIDE)

__device__ __forceinline__ void attn_issue_stage(
    uint32_t sbase, int buf,
    const __half* K, const __half* V, const int* amrow, int tid)
{
    const uint32_t stg = sbase + AOFF_STG + buf * ASTG_STRIDE;
    #pragma unroll
    for (int i = 0; i < 8; i++) {
        const int idx = i * 128 + tid;        // 0..1023
        const int region = idx >> 9;          // 0:K 1:V
        const int cid = idx & 511;
        const int row = cid >> 3, c16 = cid & 7;
        const uint32_t off = row * 128 + c16 * 16;
        const uint32_t sw = off ^ ((off >> 3) & 0x70);
        const __half* src = region ? (V + row * 64 + c16 * 8) : (K + row * 64 + c16 * 8);
        cp16(stg + region * 8192 + sw, src);
    }
    if (tid < 16) cp16(stg + 16384 + tid * 16, amrow + tid * 4);
}

__global__ void __launch_bounds__(128) attn_kernel(
    const int* __restrict__ amask, const int* __restrict__ lwp, int S)
{
    extern __shared__ char asm_[];
    const uint32_t sbase = smem_to_u32(asm_);
    const int q0 = blockIdx.x * 64;
    const int h  = blockIdx.y;
    const int bz = blockIdx.z;
    const int kvh = h >> 2;
    const int LW = *lwp;
    const int tid = threadIdx.x, warp = tid >> 5, lane = tid & 31;
    const int rIn = lane & 7, mId = lane >> 3;
    const int g = lane >> 2, t = lane & 3;

    const __half* Q0 = g_q + ((size_t)(bz*NH + h)*S + q0) * HD;
    const __half* K0 = g_k + ((size_t)(bz*NKV + kvh)*S) * HD;
    const __half* V0 = g_v + ((size_t)(bz*NKV + kvh)*S) * HD;
    const int* am0 = amask + bz * S;

    #pragma unroll
    for (int i = 0; i < 4; i++) {
        const int idx = i * 128 + tid;
        const int row = idx >> 3, c16 = idx & 7;
        const uint32_t off = row * 128 + c16 * 16;
        const uint32_t sw = off ^ ((off >> 3) & 0x70);
        *(uint4*)(asm_ + AOFF_Q + sw) = *(const uint4*)(Q0 + row * 64 + c16 * 8);
    }

    int kmin = q0 - LW + 1; if (kmin < 0) kmin = 0;
    const int kt0 = kmin >> 6, kt1 = q0 >> 6;
    const int nt = kt1 - kt0 + 1;

    attn_issue_stage(sbase, 0, K0 + (size_t)(kt0<<6)*HD, V0 + (size_t)(kt0<<6)*HD,
                     am0 + (kt0<<6), tid);
    CP_COMMIT();
    if (nt > 1) {
        attn_issue_stage(sbase, 1, K0 + (size_t)((kt0+1)<<6)*HD, V0 + (size_t)((kt0+1)<<6)*HD,
                         am0 + ((kt0+1)<<6), tid);
        CP_COMMIT();
    }

    __syncthreads();

    uint32_t aq[4][4];
    #pragma unroll
    for (int kk = 0; kk < 4; kk++) {
        const int row = warp * 16 + (mId & 1) * 8 + rIn;
        const int colB = (kk * 16 + (mId >> 1) * 8) * 2;
        const uint32_t off = row * 128 + colB;
        const uint32_t sw = off ^ ((off >> 3) & 0x70);
        ldsm_x4(aq[kk][0], aq[kk][1], aq[kk][2], aq[kk][3], sbase + AOFF_Q + sw);
    }

    float o[8][4];
    #pragma unroll
    for (int j = 0; j < 8; j++)
        #pragma unroll
        for (int e = 0; e < 4; e++) o[j][e] = 0.f;
    float l0 = 0.f, l1 = 0.f;
    const int r0g = q0 + warp * 16 + g;
    const int r1g = r0g + 8;
    const int rowlow  = q0 + warp * 16;       // lowest q row in this warp
    const int rowhigh = rowlow + 15;

    for (int i = 0; i < nt; i++) {
        const int kt = kt0 + i, buf = i & 1;
        const int k0 = kt << 6;
        if (i + 1 < nt) { CP_WAIT(1); } else { CP_WAIT(0); }
        __syncthreads();

        const uint32_t stg = sbase + AOFF_STG + buf * ASTG_STRIDE;
        const uint32_t sK = stg, sV = stg + 8192;
        const int* sAm = (const int*)(asm_ + AOFF_STG + buf * ASTG_STRIDE + 16384);

        // warp-uniform masked-block bounds (n8 granularity for QK, k16 for PV)
        int jlo = rowlow - LW + 1 - k0;  jlo = (jlo < 0) ? 0 : (jlo >> 3);
        int jhi = (rowhigh - k0) >> 3;   jhi = (jhi > 7) ? 7 : jhi;
        const int kblo = jlo >> 1, kbhi = jhi >> 1;

        float sc[8][4];
        #pragma unroll
        for (int j = 0; j < 8; j++)
            #pragma unroll
            for (int e = 0; e < 4; e++) sc[j][e] = 0.f;

        #pragma unroll
        for (int kk = 0; kk < 4; kk++) {
            uint32_t b[8][2];
            #pragma unroll
            for (int ntp = 0; ntp < 4; ntp++) {
                if (2*ntp + 1 < jlo || 2*ntp > jhi) continue;
                const int row = ntp * 16 + (mId >> 1) * 8 + rIn;
                const int colB = (kk * 16 + (mId & 1) * 8) * 2;
                const uint32_t off = row * 128 + colB;
                const uint32_t sw = off ^ ((off >> 3) & 0x70);
                ldsm_x4(b[2*ntp][0], b[2*ntp][1], b[2*ntp+1][0], b[2*ntp+1][1], sK + sw);
            }
            #pragma unroll
            for (int j = 0; j < 8; j++) {
                if (j < jlo || j > jhi) continue;
                mma_f16(sc[j], aq[kk], b[j]);
            }
        }

        // fixed-shift softmax: p = 2^(s - SHIFT), masked -> 0.
        #pragma unroll
        for (int j = 0; j < 8; j++) {
            const int ce = 8*j + 2*t, co = ce + 1;
            const int ae = sAm[ce], ao = sAm[co];
            const int gce = k0 + ce, gco = k0 + co;
            const bool a0 = ((unsigned)(r0g - gce) < (unsigned)LW) && (ae != 0);
            const bool a1 = ((unsigned)(r0g - gco) < (unsigned)LW) && (ao != 0);
            const bool a2 = ((unsigned)(r1g - gce) < (unsigned)LW) && (ae != 0);
            const bool a3 = ((unsigned)(r1g - gco) < (unsigned)LW) && (ao != 0);
            const float p0 = a0 ? ex2(sc[j][0] - SM_SHIFT) : 0.f;
            const float p1 = a1 ? ex2(sc[j][1] - SM_SHIFT) : 0.f;
            const float p2 = a2 ? ex2(sc[j][2] - SM_SHIFT) : 0.f;
            const float p3 = a3 ? ex2(sc[j][3] - SM_SHIFT) : 0.f;
            sc[j][0] = p0; sc[j][1] = p1; sc[j][2] = p2; sc[j][3] = p3;
            l0 += p0 + p1; l1 += p2 + p3;
        }

        uint32_t pa[4][4];
        #pragma unroll
        for (int kb = 0; kb < 4; kb++) {
            const int j0 = 2*kb, j1 = 2*kb + 1;
            pa[kb][0] = pack_h2(sc[j0][0], sc[j0][1]);
            pa[kb][1] = pack_h2(sc[j0][2], sc[j0][3]);
            pa[kb][2] = pack_h2(sc[j1][0], sc[j1][1]);
            pa[kb][3] = pack_h2(sc[j1][2], sc[j1][3]);
        }

        #pragma unroll
        for (int kb = 0; kb < 4; kb++) {
            if (kb < kblo || kb > kbhi) continue;
            uint32_t v[8][2];
            #pragma unroll
            for (int dp = 0; dp < 4; dp++) {
                const int row = kb * 16 + (mId & 1) * 8 + rIn;
                const int colB = (dp * 16 + (mId >> 1) * 8) * 2;
                const uint32_t off = row * 128 + colB;
                const uint32_t sw = off ^ ((off >> 3) & 0x70);
                ldsm_x4_t(v[2*dp][0], v[2*dp][1], v[2*dp+1][0], v[2*dp+1][1], sV + sw);
            }
            #pragma unroll
            for (int j = 0; j < 8; j++)
                mma_f16(o[j], pa[kb], v[j]);
        }

        __syncthreads();
        if (i + 2 < nt) {
            const int kn = (kt + 2) << 6;
            attn_issue_stage(sbase, buf, K0 + (size_t)kn*HD, V0 + (size_t)kn*HD,
                             am0 + kn, tid);
            CP_COMMIT();
        }
    }

    l0 += __shfl_xor_sync(0xffffffffu, l0, 1);
    l0 += __shfl_xor_sync(0xffffffffu, l0, 2);
    l1 += __shfl_xor_sync(0xffffffffu, l1, 1);
    l1 += __shfl_xor_sync(0xffffffffu, l1, 2);

    const float inv0 = 1.0f / l0, inv1 = 1.0f / l1;
    const size_t tok0 = (size_t)(bz*S + r0g) * NE + h*HD;
    const size_t tok1 = (size_t)(bz*S + r1g) * NE + h*HD;
    #pragma unroll
    for (int j = 0; j < 8; j++) {
        const int d0 = 8*j + 2*t;
        *(uint32_t*)(g_y + tok0 + d0) = pack_h2(o[j][0]*inv0, o[j][1]*inv0);
        *(uint32_t*)(g_y + tok1 + d0) = pack_h2(o[j][2]*inv1, o[j][3]*inv1);
    }
}

// ---------------- launch ----------------------------------------------------
extern "C" void kernel_launch(void* const* d_in, const int* in_sizes, int n_in,
                              void* d_out, int out_size)
{
    const float* x     = (const float*)d_in[0];
    const float* ve    = (const float*)d_in[1];
    const float* cosb  = (const float*)d_in[2];
    const float* sinb  = (const float*)d_in[3];
    const float* Wq    = (const float*)d_in[4];
    const float* Wk    = (const float*)d_in[5];
    const float* Wv    = (const float*)d_in[6];
    const float* Wproj = (const float*)d_in[7];
    const float* Wgate = (const float*)d_in[8];
    const int*   amask = (const int*)d_in[9];
    const int*   lw    = (const int*)d_in[10];
    float* out = (float*)d_out;

    const int S = in_sizes[2] / 32;        // cos is (S,1,32)
    const int B = in_sizes[0] / (S * NE);
    const int M = B * S;

    __half *xp, *wp, *wpp, *yp;
    cudaGetSymbolAddress((void**)&xp,  g_x);
    cudaGetSymbolAddress((void**)&wp,  g_w);
    cudaGetSymbolAddress((void**)&wpp, g_wp);
    cudaGetSymbolAddress((void**)&yp,  g_y);

    // merged fp32 -> fp16 converts
    const int nx4 = M * NE / 4;
    const int ntot = nx4 + 655360;
    cvt_all<<<(ntot + 255)/256, 256>>>(x, Wq, Wk, Wv, Wproj, xp, nx4);

    cudaFuncSetAttribute(gemm_qkv, cudaFuncAttributeMaxDynamicSharedMemorySize, GSMEM);
    cudaFuncSetAttribute(gemm_mma, cudaFuncAttributeMaxDynamicSharedMemorySize, GSMEM);

    // fused QKV projection + rope/rmsnorm/gate epilogue (N tiles of 64)
    gemm_qkv<<<dim3(24, M/128), 256, GSMEM>>>(xp, wp, x, ve, cosb, sinb, Wgate, S);

    // attention (tensor-core flash, fixed-shift softmax, masked-block skip)
    cudaFuncSetAttribute(attn_kernel, cudaFuncAttributeMaxDynamicSharedMemorySize, ASMEM);
    attn_kernel<<<dim3(S/64, NH, B), 128, ASMEM>>>(amask, lw, S);

    // output projection straight into d_out
    gemm_mma<<<dim3(16, M/128), 256, GSMEM>>>(yp, wpp, out, 1024);
}

// round 9
// speedup vs baseline: 1.0635x; 1.0635x over previous
#include <cuda_runtime.h>
#include <cuda_fp16.h>
#include <math.h>
#include <stdint.h>

#define NE   1024
#define NH   16
#define NKV  4
#define HD   64
#define SMAX 2048
#define BMAX 2
#define MMAX (BMAX*SMAX)
#define RMS_EPS 1.1920929e-07f
#define SM_SHIFT 13.0f

// ---------------- scratch (device globals; no allocation allowed) ----------
__device__ __half g_x[(size_t)MMAX*NE];          // x fp16
__device__ __half g_w[1536*1024];                // fused Wq|Wk|Wv fp16
__device__ __half g_wp[1024*1024];               // Wproj fp16
__device__ __half g_y[(size_t)MMAX*NE];          // attention out fp16
__device__ __half g_q[(size_t)BMAX*NH*SMAX*HD];  // roped q (scale+log2e folded)
__device__ __half g_k[(size_t)BMAX*NKV*SMAX*HD];
__device__ __half g_v[(size_t)BMAX*NKV*SMAX*HD];

// ---------------- PTX helpers (family-generic only) -------------------------
__device__ __forceinline__ uint32_t smem_to_u32(const void* p) {
    uint32_t a;
    asm("{ .reg .u64 t; cvta.to.shared.u64 t, %1; cvt.u32.u64 %0, t; }" : "=r"(a) : "l"(p));
    return a;
}
__device__ __forceinline__ void ldsm_x4(uint32_t& r0, uint32_t& r1, uint32_t& r2,
                                        uint32_t& r3, uint32_t addr) {
    asm volatile("ldmatrix.sync.aligned.m8n8.x4.shared.b16 {%0,%1,%2,%3}, [%4];"
        : "=r"(r0), "=r"(r1), "=r"(r2), "=r"(r3) : "r"(addr));
}
__device__ __forceinline__ void ldsm_x4_t(uint32_t& r0, uint32_t& r1, uint32_t& r2,
                                          uint32_t& r3, uint32_t addr) {
    asm volatile("ldmatrix.sync.aligned.m8n8.x4.trans.shared.b16 {%0,%1,%2,%3}, [%4];"
        : "=r"(r0), "=r"(r1), "=r"(r2), "=r"(r3) : "r"(addr));
}
__device__ __forceinline__ void mma_f16(float* c, const uint32_t* a, const uint32_t* b) {
    asm volatile("mma.sync.aligned.m16n8k16.row.col.f32.f16.f16.f32 "
        "{%0,%1,%2,%3}, {%4,%5,%6,%7}, {%8,%9}, {%0,%1,%2,%3};"
        : "+f"(c[0]), "+f"(c[1]), "+f"(c[2]), "+f"(c[3])
        : "r"(a[0]), "r"(a[1]), "r"(a[2]), "r"(a[3]), "r"(b[0]), "r"(b[1]));
}
__device__ __forceinline__ void cp16(uint32_t dst, const void* src) {
    asm volatile("cp.async.cg.shared.global [%0], [%1], 16;" :: "r"(dst), "l"(src));
}
#define CP_COMMIT() asm volatile("cp.async.commit_group;" ::: "memory")
#define CP_WAIT(n)  asm volatile("cp.async.wait_group %0;" :: "n"(n) : "memory")

__device__ __forceinline__ uint32_t pack_h2(float x, float y) {
    __half2 h = __floats2half2_rn(x, y);
    return *(uint32_t*)&h;
}
__device__ __forceinline__ float ex2(float x) {
    float r; asm("ex2.approx.ftz.f32 %0, %1;" : "=f"(r) : "f"(x)); return r;
}

// ---------------- merged fp32 -> fp16 convert --------------------------------
__global__ void __launch_bounds__(256) cvt_all(
    const float* __restrict__ x,  const float* __restrict__ Wq,
    const float* __restrict__ Wk, const float* __restrict__ Wv,
    const float* __restrict__ Wproj, __half* __restrict__ xo, int nx4)
{
    int i = blockIdx.x * 256 + threadIdx.x;
    const float* src;
    __half* h;
    int o;
    if (i < nx4) { src = x; h = xo; o = i; }
    else {
        i -= nx4;
        if      (i < 262144)  { src = Wq;    h = g_w;           o = i; }
        else if (i < 327680)  { src = Wk;    h = g_w + 1048576; o = i - 262144; }
        else if (i < 393216)  { src = Wv;    h = g_w + 1310720; o = i - 327680; }
        else if (i < 655360)  { src = Wproj; h = g_wp;          o = i - 393216; }
        else return;
    }
    float4 v = ((const float4*)src)[o];
    ((uint32_t*)h)[o*2]   = pack_h2(v.x, v.y);
    ((uint32_t*)h)[o*2+1] = pack_h2(v.z, v.w);
}

// ---------------- fp16 mma.sync GEMM: CTA 128x128, warp 32x64, 2 CTA/SM ------
#define STG_BYTES 32768   /* A|B regions, 16KB each */
#define GSMEM (3*STG_BYTES)

__device__ __forceinline__ void gemm_issue_stage(
    uint32_t sbase, int stg, int kc,
    const __half* __restrict__ A, const __half* __restrict__ W,
    int bm, int bn, int K, int tid)
{
    #pragma unroll
    for (int i = 0; i < 8; i++) {
        const int idx = i * 256 + tid;           // 0..2047
        const int region = idx >> 10;            // 0:A 1:W
        const int cid = idx & 1023;
        const int row = cid >> 3, c16 = cid & 7;
        const uint32_t off = row * 128 + c16 * 16;
        const uint32_t sw = off ^ ((off >> 3) & 0x70);
        const int gk = kc * 64 + c16 * 8;
        const __half* src = region ? (W + (size_t)(bn + row) * K + gk)
                                   : (A + (size_t)(bm + row) * K + gk);
        cp16(sbase + stg * STG_BYTES + region * 16384 + sw, src);
    }
}

__device__ __forceinline__ void gemm_mainloop(
    float c[2][8][4], uint32_t sbase,
    const __half* A, const __half* W, int bm, int bn, int tid)
{
    constexpr int K = 1024;
    constexpr int NK = K / 64;
    const int wid = tid >> 5, lane = tid & 31;
    const int warpM = wid & 3, warpN = wid >> 2;
    const int rIn = lane & 7, mId = lane >> 3;

    #pragma unroll
    for (int mt = 0; mt < 2; mt++)
        #pragma unroll
        for (int n = 0; n < 8; n++)
            #pragma unroll
            for (int j = 0; j < 4; j++) c[mt][n][j] = 0.f;

    gemm_issue_stage(sbase, 0, 0, A, W, bm, bn, K, tid); CP_COMMIT();
    gemm_issue_stage(sbase, 1, 1, A, W, bm, bn, K, tid); CP_COMMIT();

    for (int kc = 0; kc < NK; kc++) {
        const int stg = kc % 3;
        if (kc + 2 < NK) {
            gemm_issue_stage(sbase, (kc + 2) % 3, kc + 2, A, W, bm, bn, K, tid);
            CP_COMMIT();
            CP_WAIT(2);
        } else if (kc + 1 < NK) {
            CP_WAIT(1);
        } else {
            CP_WAIT(0);
        }
        __syncthreads();

        const uint32_t aA = sbase + stg * STG_BYTES;
        const uint32_t aB = aA + 16384;

        #pragma unroll
        for (int kk = 0; kk < 64; kk += 16) {
            uint32_t a[2][4];
            #pragma unroll
            for (int mt = 0; mt < 2; mt++) {
                const int row = warpM * 32 + mt * 16 + (mId & 1) * 8 + rIn;
                const int colB = (kk + (mId >> 1) * 8) * 2;
                const uint32_t off = row * 128 + colB;
                const uint32_t sw = off ^ ((off >> 3) & 0x70);
                ldsm_x4(a[mt][0], a[mt][1], a[mt][2], a[mt][3], aA + sw);
            }
            uint32_t b[8][2];
            #pragma unroll
            for (int nt = 0; nt < 4; nt++) {
                const int row = warpN * 64 + nt * 16 + (mId >> 1) * 8 + rIn;
                const int colB = (kk + (mId & 1) * 8) * 2;
                const uint32_t off = row * 128 + colB;
                const uint32_t sw = off ^ ((off >> 3) & 0x70);
                ldsm_x4(b[2*nt][0], b[2*nt][1], b[2*nt+1][0], b[2*nt+1][1], aB + sw);
            }
            #pragma unroll
            for (int mt = 0; mt < 2; mt++)
                #pragma unroll
                for (int n = 0; n < 8; n++)
                    mma_f16(c[mt][n], a[mt], b[n]);
        }
        __syncthreads();
    }
}

// ---------------- proj GEMM (fp32 out) ---------------------------------------
__global__ void __launch_bounds__(256, 2) gemm_mma(
    const __half* __restrict__ A, const __half* __restrict__ W,
    float* __restrict__ C, int ldc)
{
    extern __shared__ char gsm[];
    const uint32_t sbase = smem_to_u32(gsm);
    const int tid = threadIdx.x, wid = tid >> 5, lane = tid & 31;
    const int warpM = wid & 3, warpN = wid >> 2;
    const int bm = blockIdx.y * 128, bn = blockIdx.x * 128;

    float c[2][8][4];
    gemm_mainloop(c, sbase, A, W, bm, bn, tid);

    const int g = lane >> 2, t = lane & 3;
    #pragma unroll
    for (int mt = 0; mt < 2; mt++) {
        #pragma unroll
        for (int n = 0; n < 8; n++) {
            const int r0 = bm + warpM * 32 + mt * 16 + g;
            const int col = bn + warpN * 64 + n * 8 + t * 2;
            *(float2*)&C[(size_t)r0 * ldc + col]       = make_float2(c[mt][n][0], c[mt][n][1]);
            *(float2*)&C[(size_t)(r0 + 8) * ldc + col] = make_float2(c[mt][n][2], c[mt][n][3]);
        }
    }
}

// ---------------- QKV GEMM with fused rope/rmsnorm/gate epilogue -------------
__global__ void __launch_bounds__(256, 2) gemm_qkv(
    const __half* __restrict__ A, const __half* __restrict__ W,
    const float* __restrict__ x, const float* __restrict__ ve,
    const float* __restrict__ cosb, const float* __restrict__ sinb,
    const float* __restrict__ Wgate, int S)
{
    extern __shared__ char gsm[];
    const uint32_t sbase = smem_to_u32(gsm);
    const int tid = threadIdx.x, wid = tid >> 5, lane = tid & 31;
    const int warpM = wid & 3, warpN = wid >> 2;
    const int bm = blockIdx.y * 128, bn = blockIdx.x * 128;

    float c[2][8][4];
    gemm_mainloop(c, sbase, A, W, bm, bn, tid);

    const int g = lane >> 2, t = lane & 3;
    const int colbase = bn + warpN * 64;
    const int type = (colbase < 1024) ? 0 : (colbase < 1280 ? 1 : 2);
    // q gets softmax scale and log2(e) folded in; k gets plain 1.2
    const float sQK = (type == 0) ? (1.2f * 0.125f * 1.44269504f) : 1.2f;

    #pragma unroll
    for (int mt = 0; mt < 2; mt++) {
        #pragma unroll
        for (int e = 0; e < 2; e++) {
            const int row = warpM * 32 + mt * 16 + g + e * 8;
            const int m = bm + row;
            const int b = m / S, s = m - b * S;
            if (type <= 1) {
                float r1[4][2], r2[4][2];
                float ss = 0.f;
                #pragma unroll
                for (int n = 0; n < 4; n++) {
                    const int d0 = n * 8 + 2 * t;
                    const float cs0 = cosb[s*32 + d0], cs1 = cosb[s*32 + d0 + 1];
                    const float sn0 = sinb[s*32 + d0], sn1 = sinb[s*32 + d0 + 1];
                    const float t1a = c[mt][n][2*e],   t1b = c[mt][n][2*e+1];
                    const float t2a = c[mt][n+4][2*e], t2b = c[mt][n+4][2*e+1];
                    r1[n][0] = t1a*cs0 + t2a*sn0;  r1[n][1] = t1b*cs1 + t2b*sn1;
                    r2[n][0] = t2a*cs0 - t1a*sn0;  r2[n][1] = t2b*cs1 - t1b*sn1;
                    ss += r1[n][0]*r1[n][0] + r1[n][1]*r1[n][1]
                        + r2[n][0]*r2[n][0] + r2[n][1]*r2[n][1];
                }
                ss += __shfl_xor_sync(0xffffffffu, ss, 1);
                ss += __shfl_xor_sync(0xffffffffu, ss, 2);
                const float inv = rsqrtf(ss * (1.0f/64.0f) + RMS_EPS) * sQK;
                __half* dst;
                size_t doff;
                if (type == 0) {
                    const int hh = colbase >> 6;
                    doff = ((size_t)(b*NH + hh)*S + s) * HD;
                    dst = g_q;
                } else {
                    const int kh = (colbase - 1024) >> 6;
                    doff = ((size_t)(b*NKV + kh)*S + s) * HD;
                    dst = g_k;
                }
                #pragma unroll
                for (int n = 0; n < 4; n++) {
                    const int d0 = n * 8 + 2 * t;
                    *(uint32_t*)(dst + doff + d0)      = pack_h2(r1[n][0]*inv, r1[n][1]*inv);
                    *(uint32_t*)(dst + doff + d0 + 32) = pack_h2(r2[n][0]*inv, r2[n][1]*inv);
                }
            } else {
                const int kvh = (colbase - 1280) >> 6;
                float gz = 0.f;
                #pragma unroll
                for (int j = 0; j < 3; j++)
                    gz += x[(size_t)m*NE + 3*t + j] * Wgate[kvh*12 + 3*t + j];
                gz += __shfl_xor_sync(0xffffffffu, gz, 1);
                gz += __shfl_xor_sync(0xffffffffu, gz, 2);
                const float gate = 3.0f / (1.0f + __expf(-gz));
                const size_t doff = ((size_t)(b*NKV + kvh)*S + s) * HD;
                const float* vep = ve + (size_t)m*256 + kvh*64;
                #pragma unroll
                for (int n = 0; n < 8; n++) {
                    const int d0 = n * 8 + 2 * t;
                    const float v0 = c[mt][n][2*e]   + gate * vep[d0];
                    const float v1 = c[mt][n][2*e+1] + gate * vep[d0+1];
                    *(uint32_t*)(g_v + doff + d0) = pack_h2(v0, v1);
                }
            }
        }
    }
}

// ---------------- flash attention, fixed-shift softmax + block skip ----------
#define AOFF_Q   0
#define AOFF_STG 8192
#define ASTG_STRIDE 16640   /* K (8KB) + V (8KB) + amask (256B) */
#define ASMEM (AOFF_STG + 2*ASTG_STRIDE)

__device__ __forceinline__ void attn_issue_stage(
    uint32_t sbase, int buf,
    const __half* K, const __half* V, const int* amrow, int tid)
{
    const uint32_t stg = sbase + AOFF_STG + buf * ASTG_STRIDE;
    #pragma unroll
    for (int i = 0; i < 8; i++) {
        const int idx = i * 128 + tid;        // 0..1023
        const int region = idx >> 9;          // 0:K 1:V
        const int cid = idx & 511;
        const int row = cid >> 3, c16 = cid & 7;
        const uint32_t off = row * 128 + c16 * 16;
        const uint32_t sw = off ^ ((off >> 3) & 0x70);
        const __half* src = region ? (V + row * 64 + c16 * 8) : (K + row * 64 + c16 * 8);
        cp16(stg + region * 8192 + sw, src);
    }
    if (tid < 16) cp16(stg + 16384 + tid * 16, amrow + tid * 4);
}

__global__ void __launch_bounds__(128) attn_kernel(
    const int* __restrict__ amask, const int* __restrict__ lwp, int S)
{
    extern __shared__ char asm_[];
    const uint32_t sbase = smem_to_u32(asm_);
    const int q0 = blockIdx.x * 64;
    const int h  = blockIdx.y;
    const int bz = blockIdx.z;
    const int kvh = h >> 2;
    const int LW = *lwp;
    const int tid = threadIdx.x, warp = tid >> 5, lane = tid & 31;
    const int rIn = lane & 7, mId = lane >> 3;
    const int g = lane >> 2, t = lane & 3;

    const __half* Q0 = g_q + ((size_t)(bz*NH + h)*S + q0) * HD;
    const __half* K0 = g_k + ((size_t)(bz*NKV + kvh)*S) * HD;
    const __half* V0 = g_v + ((size_t)(bz*NKV + kvh)*S) * HD;
    const int* am0 = amask + bz * S;

    #pragma unroll
    for (int i = 0; i < 4; i++) {
        const int idx = i * 128 + tid;
        const int row = idx >> 3, c16 = idx & 7;
        const uint32_t off = row * 128 + c16 * 16;
        const uint32_t sw = off ^ ((off >> 3) & 0x70);
        *(uint4*)(asm_ + AOFF_Q + sw) = *(const uint4*)(Q0 + row * 64 + c16 * 8);
    }

    int kmin = q0 - LW + 1; if (kmin < 0) kmin = 0;
    const int kt0 = kmin >> 6, kt1 = q0 >> 6;
    const int nt = kt1 - kt0 + 1;

    attn_issue_stage(sbase, 0, K0 + (size_t)(kt0<<6)*HD, V0 + (size_t)(kt0<<6)*HD,
                     am0 + (kt0<<6), tid);
    CP_COMMIT();
    if (nt > 1) {
        attn_issue_stage(sbase, 1, K0 + (size_t)((kt0+1)<<6)*HD, V0 + (size_t)((kt0+1)<<6)*HD,
                         am0 + ((kt0+1)<<6), tid);
        CP_COMMIT();
    }

    __syncthreads();

    uint32_t aq[4][4];
    #pragma unroll
    for (int kk = 0; kk < 4; kk++) {
        const int row = warp * 16 + (mId & 1) * 8 + rIn;
        const int colB = (kk * 16 + (mId >> 1) * 8) * 2;
        const uint32_t off = row * 128 + colB;
        const uint32_t sw = off ^ ((off >> 3) & 0x70);
        ldsm_x4(aq[kk][0], aq[kk][1], aq[kk][2], aq[kk][3], sbase + AOFF_Q + sw);
    }

    float o[8][4];
    #pragma unroll
    for (int j = 0; j < 8; j++)
        #pragma unroll
        for (int e = 0; e < 4; e++) o[j][e] = 0.f;
    float l0 = 0.f, l1 = 0.f;
    const int r0g = q0 + warp * 16 + g;
    const int r1g = r0g + 8;
    const int rowlow  = q0 + warp * 16;
    const int rowhigh = rowlow + 15;

    for (int i = 0; i < nt; i++) {
        const int kt = kt0 + i, buf = i & 1;
        const int k0 = kt << 6;
        if (i + 1 < nt) { CP_WAIT(1); } else { CP_WAIT(0); }
        __syncthreads();

        const uint32_t stg = sbase + AOFF_STG + buf * ASTG_STRIDE;
        const uint32_t sK = stg, sV = stg + 8192;
        const int* sAm = (const int*)(asm_ + AOFF_STG + buf * ASTG_STRIDE + 16384);

        // warp-uniform masked-block bounds (n8 granularity for QK, k16 for PV)
        int jlo = rowlow - LW + 1 - k0;  jlo = (jlo < 0) ? 0 : (jlo >> 3);
        int jhi = (rowhigh - k0) >> 3;   jhi = (jhi > 7) ? 7 : jhi;
        const int kblo = jlo >> 1, kbhi = jhi >> 1;

        float sc[8][4];
        #pragma unroll
        for (int j = 0; j < 8; j++)
            #pragma unroll
            for (int e = 0; e < 4; e++) sc[j][e] = 0.f;

        #pragma unroll
        for (int kk = 0; kk < 4; kk++) {
            uint32_t b[8][2];
            #pragma unroll
            for (int ntp = 0; ntp < 4; ntp++) {
                if (2*ntp + 1 < jlo || 2*ntp > jhi) continue;
                const int row = ntp * 16 + (mId >> 1) * 8 + rIn;
                const int colB = (kk * 16 + (mId & 1) * 8) * 2;
                const uint32_t off = row * 128 + colB;
                const uint32_t sw = off ^ ((off >> 3) & 0x70);
                ldsm_x4(b[2*ntp][0], b[2*ntp][1], b[2*ntp+1][0], b[2*ntp+1][1], sK + sw);
            }
            #pragma unroll
            for (int j = 0; j < 8; j++) {
                if (j < jlo || j > jhi) continue;
                mma_f16(sc[j], aq[kk], b[j]);
            }
        }

        // fixed-shift softmax: p = 2^(s - SHIFT), masked -> 0.
        #pragma unroll
        for (int j = 0; j < 8; j++) {
            const int ce = 8*j + 2*t, co = ce + 1;
            const int ae = sAm[ce], ao = sAm[co];
            const int gce = k0 + ce, gco = k0 + co;
            const bool a0 = ((unsigned)(r0g - gce) < (unsigned)LW) && (ae != 0);
            const bool a1 = ((unsigned)(r0g - gco) < (unsigned)LW) && (ao != 0);
            const bool a2 = ((unsigned)(r1g - gce) < (unsigned)LW) && (ae != 0);
            const bool a3 = ((unsigned)(r1g - gco) < (unsigned)LW) && (ao != 0);
            const float p0 = a0 ? ex2(sc[j][0] - SM_SHIFT) : 0.f;
            const float p1 = a1 ? ex2(sc[j][1] - SM_SHIFT) : 0.f;
            const float p2 = a2 ? ex2(sc[j][2] - SM_SHIFT) : 0.f;
            const float p3 = a3 ? ex2(sc[j][3] - SM_SHIFT) : 0.f;
            sc[j][0] = p0; sc[j][1] = p1; sc[j][2] = p2; sc[j][3] = p3;
            l0 += p0 + p1; l1 += p2 + p3;
        }

        uint32_t pa[4][4];
        #pragma unroll
        for (int kb = 0; kb < 4; kb++) {
            const int j0 = 2*kb, j1 = 2*kb + 1;
            pa[kb][0] = pack_h2(sc[j0][0], sc[j0][1]);
            pa[kb][1] = pack_h2(sc[j0][2], sc[j0][3]);
            pa[kb][2] = pack_h2(sc[j1][0], sc[j1][1]);
            pa[kb][3] = pack_h2(sc[j1][2], sc[j1][3]);
        }

        #pragma unroll
        for (int kb = 0; kb < 4; kb++) {
            if (kb < kblo || kb > kbhi) continue;
            uint32_t v[8][2];
            #pragma unroll
            for (int dp = 0; dp < 4; dp++) {
                const int row = kb * 16 + (mId & 1) * 8 + rIn;
                const int colB = (dp * 16 + (mId >> 1) * 8) * 2;
                const uint32_t off = row * 128 + colB;
                const uint32_t sw = off ^ ((off >> 3) & 0x70);
                ldsm_x4_t(v[2*dp][0], v[2*dp][1], v[2*dp+1][0], v[2*dp+1][1], sV + sw);
            }
            #pragma unroll
            for (int j = 0; j < 8; j++)
                mma_f16(o[j], pa[kb], v[j]);
        }

        __syncthreads();
        if (i + 2 < nt) {
            const int kn = (kt + 2) << 6;
            attn_issue_stage(sbase, buf, K0 + (size_t)kn*HD, V0 + (size_t)kn*HD,
                             am0 + kn, tid);
            CP_COMMIT();
        }
    }

    l0 += __shfl_xor_sync(0xffffffffu, l0, 1);
    l0 += __shfl_xor_sync(0xffffffffu, l0, 2);
    l1 += __shfl_xor_sync(0xffffffffu, l1, 1);
    l1 += __shfl_xor_sync(0xffffffffu, l1, 2);

    const float inv0 = 1.0f / l0, inv1 = 1.0f / l1;
    const size_t tok0 = (size_t)(bz*S + r0g) * NE + h*HD;
    const size_t tok1 = (size_t)(bz*S + r1g) * NE + h*HD;
    #pragma unroll
    for (int j = 0; j < 8; j++) {
        const int d0 = 8*j + 2*t;
        *(uint32_t*)(g_y + tok0 + d0) = pack_h2(o[j][0]*inv0, o[j][1]*inv0);
        *(uint32_t*)(g_y + tok1 + d0) = pack_h2(o[j][2]*inv1, o[j][3]*inv1);
    }
}

// ---------------- launch ----------------------------------------------------
extern "C" void kernel_launch(void* const* d_in, const int* in_sizes, int n_in,
                              void* d_out, int out_size)
{
    const float* x     = (const float*)d_in[0];
    const float* ve    = (const float*)d_in[1];
    const float* cosb  = (const float*)d_in[2];
    const float* sinb  = (const float*)d_in[3];
    const float* Wq    = (const float*)d_in[4];
    const float* Wk    = (const float*)d_in[5];
    const float* Wv    = (const float*)d_in[6];
    const float* Wproj = (const float*)d_in[7];
    const float* Wgate = (const float*)d_in[8];
    const int*   amask = (const int*)d_in[9];
    const int*   lw    = (const int*)d_in[10];
    float* out = (float*)d_out;

    const int S = in_sizes[2] / 32;        // cos is (S,1,32)
    const int B = in_sizes[0] / (S * NE);
    const int M = B * S;

    __half *xp, *wp, *wpp, *yp;
    cudaGetSymbolAddress((void**)&xp,  g_x);
    cudaGetSymbolAddress((void**)&wp,  g_w);
    cudaGetSymbolAddress((void**)&wpp, g_wp);
    cudaGetSymbolAddress((void**)&yp,  g_y);

    // merged fp32 -> fp16 converts
    const int nx4 = M * NE / 4;
    const int ntot = nx4 + 655360;
    cvt_all<<<(ntot + 255)/256, 256>>>(x, Wq, Wk, Wv, Wproj, xp, nx4);

    cudaFuncSetAttribute(gemm_qkv, cudaFuncAttributeMaxDynamicSharedMemorySize, GSMEM);
    cudaFuncSetAttribute(gemm_mma, cudaFuncAttributeMaxDynamicSharedMemorySize, GSMEM);

    // fused QKV projection + rope/rmsnorm/gate epilogue
    gemm_qkv<<<dim3(12, M/128), 256, GSMEM>>>(xp, wp, x, ve, cosb, sinb, Wgate, S);

    // attention (tensor-core flash, fixed-shift softmax, masked-block skip)
    cudaFuncSetAttribute(attn_kernel, cudaFuncAttributeMaxDynamicSharedMemorySize, ASMEM);
    attn_kernel<<<dim3(S/64, NH, B), 128, ASMEM>>>(amask, lw, S);

    // output projection straight into d_out
    gemm_mma<<<dim3(8, M/128), 256, GSMEM>>>(yp, wpp, out, 1024);
}

// round 10
// speedup vs baseline: 1.0930x; 1.0278x over previous
#include <cuda_runtime.h>
#include <cuda_fp16.h>
#include <math.h>
#include <stdint.h>

#define NE   1024
#define NH   16
#define NKV  4
#define HD   64
#define SMAX 2048
#define BMAX 2
#define MMAX (BMAX*SMAX)
#define RMS_EPS 1.1920929e-07f
#define SM_SHIFT 13.0f

// ---------------- scratch (device globals; no allocation allowed) ----------
__device__ __half g_x[(size_t)MMAX*NE];          // x fp16
__device__ __half g_w[1536*1024];                // fused Wq|Wk|Wv fp16
__device__ __half g_wp[1024*1024];               // Wproj fp16
__device__ __half g_y[(size_t)MMAX*NE];          // attention out fp16
__device__ __half g_q[(size_t)BMAX*NH*SMAX*HD];  // roped q (scale+log2e folded)
__device__ __half g_k[(size_t)BMAX*NKV*SMAX*HD];
__device__ __half g_v[(size_t)BMAX*NKV*SMAX*HD];

// ---------------- PTX helpers (family-generic only) -------------------------
__device__ __forceinline__ uint32_t smem_to_u32(const void* p) {
    uint32_t a;
    asm("{ .reg .u64 t; cvta.to.shared.u64 t, %1; cvt.u32.u64 %0, t; }" : "=r"(a) : "l"(p));
    return a;
}
__device__ __forceinline__ void ldsm_x4(uint32_t& r0, uint32_t& r1, uint32_t& r2,
                                        uint32_t& r3, uint32_t addr) {
    asm volatile("ldmatrix.sync.aligned.m8n8.x4.shared.b16 {%0,%1,%2,%3}, [%4];"
        : "=r"(r0), "=r"(r1), "=r"(r2), "=r"(r3) : "r"(addr));
}
__device__ __forceinline__ void ldsm_x4_t(uint32_t& r0, uint32_t& r1, uint32_t& r2,
                                          uint32_t& r3, uint32_t addr) {
    asm volatile("ldmatrix.sync.aligned.m8n8.x4.trans.shared.b16 {%0,%1,%2,%3}, [%4];"
        : "=r"(r0), "=r"(r1), "=r"(r2), "=r"(r3) : "r"(addr));
}
__device__ __forceinline__ void mma_f16(float* c, const uint32_t* a, const uint32_t* b) {
    asm volatile("mma.sync.aligned.m16n8k16.row.col.f32.f16.f16.f32 "
        "{%0,%1,%2,%3}, {%4,%5,%6,%7}, {%8,%9}, {%0,%1,%2,%3};"
        : "+f"(c[0]), "+f"(c[1]), "+f"(c[2]), "+f"(c[3])
        : "r"(a[0]), "r"(a[1]), "r"(a[2]), "r"(a[3]), "r"(b[0]), "r"(b[1]));
}
__device__ __forceinline__ void cp16(uint32_t dst, const void* src) {
    asm volatile("cp.async.cg.shared.global [%0], [%1], 16;" :: "r"(dst), "l"(src));
}
#define CP_COMMIT() asm volatile("cp.async.commit_group;" ::: "memory")
#define CP_WAIT(n)  asm volatile("cp.async.wait_group %0;" :: "n"(n) : "memory")

__device__ __forceinline__ uint32_t pack_h2(float x, float y) {
    __half2 h = __floats2half2_rn(x, y);
    return *(uint32_t*)&h;
}
__device__ __forceinline__ float ex2(float x) {
    float r; asm("ex2.approx.ftz.f32 %0, %1;" : "=f"(r) : "f"(x)); return r;
}

// ---------------- merged fp32 -> fp16 convert --------------------------------
__global__ void __launch_bounds__(256) cvt_all(
    const float* __restrict__ x,  const float* __restrict__ Wq,
    const float* __restrict__ Wk, const float* __restrict__ Wv,
    const float* __restrict__ Wproj, __half* __restrict__ xo, int nx4)
{
    int i = blockIdx.x * 256 + threadIdx.x;
    const float* src;
    __half* h;
    int o;
    if (i < nx4) { src = x; h = xo; o = i; }
    else {
        i -= nx4;
        if      (i < 262144)  { src = Wq;    h = g_w;           o = i; }
        else if (i < 327680)  { src = Wk;    h = g_w + 1048576; o = i - 262144; }
        else if (i < 393216)  { src = Wv;    h = g_w + 1310720; o = i - 327680; }
        else if (i < 655360)  { src = Wproj; h = g_wp;          o = i - 393216; }
        else return;
    }
    float4 v = ((const float4*)src)[o];
    ((uint32_t*)h)[o*2]   = pack_h2(v.x, v.y);
    ((uint32_t*)h)[o*2+1] = pack_h2(v.z, v.w);
}

// ---------------- fp16 mma.sync GEMM: CTA 128x128, warp 64x64, 4 warps -------
// 128 threads, 2 CTA/SM. Ratio 4 MMA per ldmatrix (round-5 calibrated regime).
#define STG_BYTES 32768   /* A|B regions, 16KB each */
#define GSMEM (3*STG_BYTES)

__device__ __forceinline__ void gemm_issue_stage(
    uint32_t sbase, int stg, int kc,
    const __half* __restrict__ A, const __half* __restrict__ W,
    int bm, int bn, int K, int tid)
{
    #pragma unroll
    for (int i = 0; i < 16; i++) {
        const int idx = i * 128 + tid;           // 0..2047
        const int region = idx >> 10;            // 0:A 1:W
        const int cid = idx & 1023;
        const int row = cid >> 3, c16 = cid & 7;
        const uint32_t off = row * 128 + c16 * 16;
        const uint32_t sw = off ^ ((off >> 3) & 0x70);
        const int gk = kc * 64 + c16 * 8;
        const __half* src = region ? (W + (size_t)(bn + row) * K + gk)
                                   : (A + (size_t)(bm + row) * K + gk);
        cp16(sbase + stg * STG_BYTES + region * 16384 + sw, src);
    }
}

// warp tile 64x64: c[4][8][4]; per k16 step: 4 A-ldsm + 4 B-ldsm, 32 MMA.
__device__ __forceinline__ void gemm_mainloop(
    float c[4][8][4], uint32_t sbase,
    const __half* A, const __half* W, int bm, int bn, int tid)
{
    constexpr int K = 1024;
    constexpr int NK = K / 64;
    const int wid = tid >> 5, lane = tid & 31;
    const int warpM = wid & 1, warpN = wid >> 1;     // 2 x 2 warps
    const int rIn = lane & 7, mId = lane >> 3;

    #pragma unroll
    for (int mt = 0; mt < 4; mt++)
        #pragma unroll
        for (int n = 0; n < 8; n++)
            #pragma unroll
            for (int j = 0; j < 4; j++) c[mt][n][j] = 0.f;

    gemm_issue_stage(sbase, 0, 0, A, W, bm, bn, K, tid); CP_COMMIT();
    gemm_issue_stage(sbase, 1, 1, A, W, bm, bn, K, tid); CP_COMMIT();

    for (int kc = 0; kc < NK; kc++) {
        const int stg = kc % 3;
        if (kc + 2 < NK) {
            gemm_issue_stage(sbase, (kc + 2) % 3, kc + 2, A, W, bm, bn, K, tid);
            CP_COMMIT();
            CP_WAIT(2);
        } else if (kc + 1 < NK) {
            CP_WAIT(1);
        } else {
            CP_WAIT(0);
        }
        __syncthreads();

        const uint32_t aA = sbase + stg * STG_BYTES;
        const uint32_t aB = aA + 16384;

        #pragma unroll
        for (int kk = 0; kk < 64; kk += 16) {
            uint32_t a[4][4];
            #pragma unroll
            for (int mt = 0; mt < 4; mt++) {
                const int row = warpM * 64 + mt * 16 + (mId & 1) * 8 + rIn;
                const int colB = (kk + (mId >> 1) * 8) * 2;
                const uint32_t off = row * 128 + colB;
                const uint32_t sw = off ^ ((off >> 3) & 0x70);
                ldsm_x4(a[mt][0], a[mt][1], a[mt][2], a[mt][3], aA + sw);
            }
            uint32_t b[8][2];
            #pragma unroll
            for (int nt = 0; nt < 4; nt++) {
                const int row = warpN * 64 + nt * 16 + (mId >> 1) * 8 + rIn;
                const int colB = (kk + (mId & 1) * 8) * 2;
                const uint32_t off = row * 128 + colB;
                const uint32_t sw = off ^ ((off >> 3) & 0x70);
                ldsm_x4(b[2*nt][0], b[2*nt][1], b[2*nt+1][0], b[2*nt+1][1], aB + sw);
            }
            #pragma unroll
            for (int mt = 0; mt < 4; mt++)
                #pragma unroll
                for (int n = 0; n < 8; n++)
                    mma_f16(c[mt][n], a[mt], b[n]);
        }
        __syncthreads();
    }
}

// ---------------- proj GEMM (fp32 out) ---------------------------------------
__global__ void __launch_bounds__(128, 2) gemm_mma(
    const __half* __restrict__ A, const __half* __restrict__ W,
    float* __restrict__ C, int ldc)
{
    extern __shared__ char gsm[];
    const uint32_t sbase = smem_to_u32(gsm);
    const int tid = threadIdx.x, wid = tid >> 5, lane = tid & 31;
    const int warpM = wid & 1, warpN = wid >> 1;
    const int bm = blockIdx.y * 128, bn = blockIdx.x * 128;

    float c[4][8][4];
    gemm_mainloop(c, sbase, A, W, bm, bn, tid);

    const int g = lane >> 2, t = lane & 3;
    #pragma unroll
    for (int mt = 0; mt < 4; mt++) {
        #pragma unroll
        for (int n = 0; n < 8; n++) {
            const int r0 = bm + warpM * 64 + mt * 16 + g;
            const int col = bn + warpN * 64 + n * 8 + t * 2;
            *(float2*)&C[(size_t)r0 * ldc + col]       = make_float2(c[mt][n][0], c[mt][n][1]);
            *(float2*)&C[(size_t)(r0 + 8) * ldc + col] = make_float2(c[mt][n][2], c[mt][n][3]);
        }
    }
}

// ---------------- QKV GEMM with fused rope/rmsnorm/gate epilogue -------------
// warpN (0/1) selects a 64-col chunk == exactly one head.
__global__ void __launch_bounds__(128, 2) gemm_qkv(
    const __half* __restrict__ A, const __half* __restrict__ W,
    const float* __restrict__ x, const float* __restrict__ ve,
    const float* __restrict__ cosb, const float* __restrict__ sinb,
    const float* __restrict__ Wgate, int S)
{
    extern __shared__ char gsm[];
    const uint32_t sbase = smem_to_u32(gsm);
    const int tid = threadIdx.x, wid = tid >> 5, lane = tid & 31;
    const int warpM = wid & 1, warpN = wid >> 1;
    const int bm = blockIdx.y * 128, bn = blockIdx.x * 128;

    float c[4][8][4];
    gemm_mainloop(c, sbase, A, W, bm, bn, tid);

    const int g = lane >> 2, t = lane & 3;
    const int colbase = bn + warpN * 64;
    const int type = (colbase < 1024) ? 0 : (colbase < 1280 ? 1 : 2);
    // q gets softmax scale and log2(e) folded in; k gets plain 1.2
    const float sQK = (type == 0) ? (1.2f * 0.125f * 1.44269504f) : 1.2f;

    #pragma unroll
    for (int mt = 0; mt < 4; mt++) {
        #pragma unroll
        for (int e = 0; e < 2; e++) {
            const int row = warpM * 64 + mt * 16 + g + e * 8;
            const int m = bm + row;
            const int b = m / S, s = m - b * S;
            if (type <= 1) {
                float r1[4][2], r2[4][2];
                float ss = 0.f;
                #pragma unroll
                for (int n = 0; n < 4; n++) {
                    const int d0 = n * 8 + 2 * t;
                    const float cs0 = cosb[s*32 + d0], cs1 = cosb[s*32 + d0 + 1];
                    const float sn0 = sinb[s*32 + d0], sn1 = sinb[s*32 + d0 + 1];
                    const float t1a = c[mt][n][2*e],   t1b = c[mt][n][2*e+1];
                    const float t2a = c[mt][n+4][2*e], t2b = c[mt][n+4][2*e+1];
                    r1[n][0] = t1a*cs0 + t2a*sn0;  r1[n][1] = t1b*cs1 + t2b*sn1;
                    r2[n][0] = t2a*cs0 - t1a*sn0;  r2[n][1] = t2b*cs1 - t1b*sn1;
                    ss += r1[n][0]*r1[n][0] + r1[n][1]*r1[n][1]
                        + r2[n][0]*r2[n][0] + r2[n][1]*r2[n][1];
                }
                ss += __shfl_xor_sync(0xffffffffu, ss, 1);
                ss += __shfl_xor_sync(0xffffffffu, ss, 2);
                const float inv = rsqrtf(ss * (1.0f/64.0f) + RMS_EPS) * sQK;
                __half* dst;
                size_t doff;
                if (type == 0) {
                    const int hh = colbase >> 6;
                    doff = ((size_t)(b*NH + hh)*S + s) * HD;
                    dst = g_q;
                } else {
                    const int kh = (colbase - 1024) >> 6;
                    doff = ((size_t)(b*NKV + kh)*S + s) * HD;
                    dst = g_k;
                }
                #pragma unroll
                for (int n = 0; n < 4; n++) {
                    const int d0 = n * 8 + 2 * t;
                    *(uint32_t*)(dst + doff + d0)      = pack_h2(r1[n][0]*inv, r1[n][1]*inv);
                    *(uint32_t*)(dst + doff + d0 + 32) = pack_h2(r2[n][0]*inv, r2[n][1]*inv);
                }
            } else {
                const int kvh = (colbase - 1280) >> 6;
                float gz = 0.f;
                #pragma unroll
                for (int j = 0; j < 3; j++)
                    gz += x[(size_t)m*NE + 3*t + j] * Wgate[kvh*12 + 3*t + j];
                gz += __shfl_xor_sync(0xffffffffu, gz, 1);
                gz += __shfl_xor_sync(0xffffffffu, gz, 2);
                const float gate = 3.0f / (1.0f + __expf(-gz));
                const size_t doff = ((size_t)(b*NKV + kvh)*S + s) * HD;
                const float* vep = ve + (size_t)m*256 + kvh*64;
                #pragma unroll
                for (int n = 0; n < 8; n++) {
                    const int d0 = n * 8 + 2 * t;
                    const float v0 = c[mt][n][2*e]   + gate * vep[d0];
                    const float v1 = c[mt][n][2*e+1] + gate * vep[d0+1];
                    *(uint32_t*)(g_v + doff + d0) = pack_h2(v0, v1);
                }
            }
        }
    }
}

// ---------------- flash attention, fixed-shift softmax (round-7 exact) -------
#define AOFF_Q   0
#define AOFF_STG 8192
#define ASTG_STRIDE 16640   /* K (8KB) + V (8KB) + amask (256B) */
#define ASMEM (AOFF_STG + 2*ASTG_STRIDE)

__device__ __forceinline__ void attn_issue_stage(
    uint32_t sbase, int buf,
    const __half* K, const __half* V, const int* amrow, int tid)
{
    const uint32_t stg = sbase + AOFF_STG + buf * ASTG_STRIDE;
    #pragma unroll
    for (int i = 0; i < 8; i++) {
        const int idx = i * 128 + tid;        // 0..1023
        const int region = idx >> 9;          // 0:K 1:V
        const int cid = idx & 511;
        const int row = cid >> 3, c16 = cid & 7;
        const uint32_t off = row * 128 + c16 * 16;
        const uint32_t sw = off ^ ((off >> 3) & 0x70);
        const __half* src = region ? (V + row * 64 + c16 * 8) : (K + row * 64 + c16 * 8);
        cp16(stg + region * 8192 + sw, src);
    }
    if (tid < 16) cp16(stg + 16384 + tid * 16, amrow + tid * 4);
}

__global__ void __launch_bounds__(128) attn_kernel(
    const int* __restrict__ amask, const int* __restrict__ lwp, int S)
{
    extern __shared__ char asm_[];
    const uint32_t sbase = smem_to_u32(asm_);
    const int q0 = blockIdx.x * 64;
    const int h  = blockIdx.y;
    const int bz = blockIdx.z;
    const int kvh = h >> 2;
    const int LW = *lwp;
    const int tid = threadIdx.x, warp = tid >> 5, lane = tid & 31;
    const int rIn = lane & 7, mId = lane >> 3;
    const int g = lane >> 2, t = lane & 3;

    const __half* Q0 = g_q + ((size_t)(bz*NH + h)*S + q0) * HD;
    const __half* K0 = g_k + ((size_t)(bz*NKV + kvh)*S) * HD;
    const __half* V0 = g_v + ((size_t)(bz*NKV + kvh)*S) * HD;
    const int* am0 = amask + bz * S;

    #pragma unroll
    for (int i = 0; i < 4; i++) {
        const int idx = i * 128 + tid;
        const int row = idx >> 3, c16 = idx & 7;
        const uint32_t off = row * 128 + c16 * 16;
        const uint32_t sw = off ^ ((off >> 3) & 0x70);
        *(uint4*)(asm_ + AOFF_Q + sw) = *(const uint4*)(Q0 + row * 64 + c16 * 8);
    }

    int kmin = q0 - LW + 1; if (kmin < 0) kmin = 0;
    const int kt0 = kmin >> 6, kt1 = q0 >> 6;
    const int nt = kt1 - kt0 + 1;

    attn_issue_stage(sbase, 0, K0 + (size_t)(kt0<<6)*HD, V0 + (size_t)(kt0<<6)*HD,
                     am0 + (kt0<<6), tid);
    CP_COMMIT();
    if (nt > 1) {
        attn_issue_stage(sbase, 1, K0 + (size_t)((kt0+1)<<6)*HD, V0 + (size_t)((kt0+1)<<6)*HD,
                         am0 + ((kt0+1)<<6), tid);
        CP_COMMIT();
    }

    __syncthreads();

    uint32_t aq[4][4];
    #pragma unroll
    for (int kk = 0; kk < 4; kk++) {
        const int row = warp * 16 + (mId & 1) * 8 + rIn;
        const int colB = (kk * 16 + (mId >> 1) * 8) * 2;
        const uint32_t off = row * 128 + colB;
        const uint32_t sw = off ^ ((off >> 3) & 0x70);
        ldsm_x4(aq[kk][0], aq[kk][1], aq[kk][2], aq[kk][3], sbase + AOFF_Q + sw);
    }

    float o[8][4];
    #pragma unroll
    for (int j = 0; j < 8; j++)
        #pragma unroll
        for (int e = 0; e < 4; e++) o[j][e] = 0.f;
    float l0 = 0.f, l1 = 0.f;
    const int r0g = q0 + warp * 16 + g;
    const int r1g = r0g + 8;

    for (int i = 0; i < nt; i++) {
        const int kt = kt0 + i, buf = i & 1;
        const int k0 = kt << 6;
        if (i + 1 < nt) { CP_WAIT(1); } else { CP_WAIT(0); }
        __syncthreads();

        const uint32_t stg = sbase + AOFF_STG + buf * ASTG_STRIDE;
        const uint32_t sK = stg, sV = stg + 8192;
        const int* sAm = (const int*)(asm_ + AOFF_STG + buf * ASTG_STRIDE + 16384);

        float sc[8][4];
        #pragma unroll
        for (int j = 0; j < 8; j++)
            #pragma unroll
            for (int e = 0; e < 4; e++) sc[j][e] = 0.f;

        #pragma unroll
        for (int kk = 0; kk < 4; kk++) {
            uint32_t b[8][2];
            #pragma unroll
            for (int ntp = 0; ntp < 4; ntp++) {
                const int row = ntp * 16 + (mId >> 1) * 8 + rIn;
                const int colB = (kk * 16 + (mId & 1) * 8) * 2;
                const uint32_t off = row * 128 + colB;
                const uint32_t sw = off ^ ((off >> 3) & 0x70);
                ldsm_x4(b[2*ntp][0], b[2*ntp][1], b[2*ntp+1][0], b[2*ntp+1][1], sK + sw);
            }
            #pragma unroll
            for (int j = 0; j < 8; j++)
                mma_f16(sc[j], aq[kk], b[j]);
        }

        // fixed-shift softmax: p = 2^(s - SHIFT), masked -> 0.
        #pragma unroll
        for (int j = 0; j < 8; j++) {
            const int ce = 8*j + 2*t, co = ce + 1;
            const int ae = sAm[ce], ao = sAm[co];
            const int gce = k0 + ce, gco = k0 + co;
            const bool a0 = ((unsigned)(r0g - gce) < (unsigned)LW) && (ae != 0);
            const bool a1 = ((unsigned)(r0g - gco) < (unsigned)LW) && (ao != 0);
            const bool a2 = ((unsigned)(r1g - gce) < (unsigned)LW) && (ae != 0);
            const bool a3 = ((unsigned)(r1g - gco) < (unsigned)LW) && (ao != 0);
            const float p0 = a0 ? ex2(sc[j][0] - SM_SHIFT) : 0.f;
            const float p1 = a1 ? ex2(sc[j][1] - SM_SHIFT) : 0.f;
            const float p2 = a2 ? ex2(sc[j][2] - SM_SHIFT) : 0.f;
            const float p3 = a3 ? ex2(sc[j][3] - SM_SHIFT) : 0.f;
            sc[j][0] = p0; sc[j][1] = p1; sc[j][2] = p2; sc[j][3] = p3;
            l0 += p0 + p1; l1 += p2 + p3;
        }

        uint32_t pa[4][4];
        #pragma unroll
        for (int kb = 0; kb < 4; kb++) {
            const int j0 = 2*kb, j1 = 2*kb + 1;
            pa[kb][0] = pack_h2(sc[j0][0], sc[j0][1]);
            pa[kb][1] = pack_h2(sc[j0][2], sc[j0][3]);
            pa[kb][2] = pack_h2(sc[j1][0], sc[j1][1]);
            pa[kb][3] = pack_h2(sc[j1][2], sc[j1][3]);
        }

        #pragma unroll
        for (int kb = 0; kb < 4; kb++) {
            uint32_t v[8][2];
            #pragma unroll
            for (int dp = 0; dp < 4; dp++) {
                const int row = kb * 16 + (mId & 1) * 8 + rIn;
                const int colB = (dp * 16 + (mId >> 1) * 8) * 2;
                const uint32_t off = row * 128 + colB;
                const uint32_t sw = off ^ ((off >> 3) & 0x70);
                ldsm_x4_t(v[2*dp][0], v[2*dp][1], v[2*dp+1][0], v[2*dp+1][1], sV + sw);
            }
            #pragma unroll
            for (int j = 0; j < 8; j++)
                mma_f16(o[j], pa[kb], v[j]);
        }

        __syncthreads();
        if (i + 2 < nt) {
            const int kn = (kt + 2) << 6;
            attn_issue_stage(sbase, buf, K0 + (size_t)kn*HD, V0 + (size_t)kn*HD,
                             am0 + kn, tid);
            CP_COMMIT();
        }
    }

    l0 += __shfl_xor_sync(0xffffffffu, l0, 1);
    l0 += __shfl_xor_sync(0xffffffffu, l0, 2);
    l1 += __shfl_xor_sync(0xffffffffu, l1, 1);
    l1 += __shfl_xor_sync(0xffffffffu, l1, 2);

    const float inv0 = 1.0f / l0, inv1 = 1.0f / l1;
    const size_t tok0 = (size_t)(bz*S + r0g) * NE + h*HD;
    const size_t tok1 = (size_t)(bz*S + r1g) * NE + h*HD;
    #pragma unroll
    for (int j = 0; j < 8; j++) {
        const int d0 = 8*j + 2*t;
        *(uint32_t*)(g_y + tok0 + d0) = pack_h2(o[j][0]*inv0, o[j][1]*inv0);
        *(uint32_t*)(g_y + tok1 + d0) = pack_h2(o[j][2]*inv1, o[j][3]*inv1);
    }
}

// ---------------- launch ----------------------------------------------------
extern "C" void kernel_launch(void* const* d_in, const int* in_sizes, int n_in,
                              void* d_out, int out_size)
{
    const float* x     = (const float*)d_in[0];
    const float* ve    = (const float*)d_in[1];
    const float* cosb  = (const float*)d_in[2];
    const float* sinb  = (const float*)d_in[3];
    const float* Wq    = (const float*)d_in[4];
    const float* Wk    = (const float*)d_in[5];
    const float* Wv    = (const float*)d_in[6];
    const float* Wproj = (const float*)d_in[7];
    const float* Wgate = (const float*)d_in[8];
    const int*   amask = (const int*)d_in[9];
    const int*   lw    = (const int*)d_in[10];
    float* out = (float*)d_out;

    const int S = in_sizes[2] / 32;        // cos is (S,1,32)
    const int B = in_sizes[0] / (S * NE);
    const int M = B * S;

    __half *xp, *wp, *wpp, *yp;
    cudaGetSymbolAddress((void**)&xp,  g_x);
    cudaGetSymbolAddress((void**)&wp,  g_w);
    cudaGetSymbolAddress((void**)&wpp, g_wp);
    cudaGetSymbolAddress((void**)&yp,  g_y);

    // merged fp32 -> fp16 converts
    const int nx4 = M * NE / 4;
    const int ntot = nx4 + 655360;
    cvt_all<<<(ntot + 255)/256, 256>>>(x, Wq, Wk, Wv, Wproj, xp, nx4);

    cudaFuncSetAttribute(gemm_qkv, cudaFuncAttributeMaxDynamicSharedMemorySize, GSMEM);
    cudaFuncSetAttribute(gemm_mma, cudaFuncAttributeMaxDynamicSharedMemorySize, GSMEM);

    // fused QKV projection + rope/rmsnorm/gate epilogue
    gemm_qkv<<<dim3(12, M/128), 128, GSMEM>>>(xp, wp, x, ve, cosb, sinb, Wgate, S);

    // attention (tensor-core flash, fixed-shift softmax)
    cudaFuncSetAttribute(attn_kernel, cudaFuncAttributeMaxDynamicSharedMemorySize, ASMEM);
    attn_kernel<<<dim3(S/64, NH, B), 128, ASMEM>>>(amask, lw, S);

    // output projection straight into d_out
    gemm_mma<<<dim3(8, M/128), 128, GSMEM>>>(yp, wpp, out, 1024);
}

// round 11
// speedup vs baseline: 1.1296x; 1.0335x over previous
#include <cuda_runtime.h>
#include <cuda_fp16.h>
#include <math.h>
#include <stdint.h>

#define NE   1024
#define NH   16
#define NKV  4
#define HD   64
#define SMAX 2048
#define BMAX 2
#define MMAX (BMAX*SMAX)
#define RMS_EPS 1.1920929e-07f
#define SM_SHIFT 13.0f

// ---------------- scratch (device globals; no allocation allowed) ----------
__device__ __half g_x[(size_t)MMAX*NE];          // x fp16
__device__ __half g_w[1536*1024];                // fused Wq|Wk|Wv fp16
__device__ __half g_wp[1024*1024];               // Wproj fp16
__device__ __half g_y[(size_t)MMAX*NE];          // attention out fp16
__device__ __half g_q[(size_t)BMAX*NH*SMAX*HD];  // roped q (scale+log2e folded)
__device__ __half g_k[(size_t)BMAX*NKV*SMAX*HD];
__device__ __half g_v[(size_t)BMAX*NKV*SMAX*HD];

// ---------------- PTX helpers (family-generic only) -------------------------
__device__ __forceinline__ uint32_t smem_to_u32(const void* p) {
    uint32_t a;
    asm("{ .reg .u64 t; cvta.to.shared.u64 t, %1; cvt.u32.u64 %0, t; }" : "=r"(a) : "l"(p));
    return a;
}
__device__ __forceinline__ void ldsm_x4(uint32_t& r0, uint32_t& r1, uint32_t& r2,
                                        uint32_t& r3, uint32_t addr) {
    asm volatile("ldmatrix.sync.aligned.m8n8.x4.shared.b16 {%0,%1,%2,%3}, [%4];"
        : "=r"(r0), "=r"(r1), "=r"(r2), "=r"(r3) : "r"(addr));
}
__device__ __forceinline__ void ldsm_x4_t(uint32_t& r0, uint32_t& r1, uint32_t& r2,
                                          uint32_t& r3, uint32_t addr) {
    asm volatile("ldmatrix.sync.aligned.m8n8.x4.trans.shared.b16 {%0,%1,%2,%3}, [%4];"
        : "=r"(r0), "=r"(r1), "=r"(r2), "=r"(r3) : "r"(addr));
}
__device__ __forceinline__ void mma_f16(float* c, const uint32_t* a, const uint32_t* b) {
    asm volatile("mma.sync.aligned.m16n8k16.row.col.f32.f16.f16.f32 "
        "{%0,%1,%2,%3}, {%4,%5,%6,%7}, {%8,%9}, {%0,%1,%2,%3};"
        : "+f"(c[0]), "+f"(c[1]), "+f"(c[2]), "+f"(c[3])
        : "r"(a[0]), "r"(a[1]), "r"(a[2]), "r"(a[3]), "r"(b[0]), "r"(b[1]));
}
__device__ __forceinline__ void cp16(uint32_t dst, const void* src) {
    asm volatile("cp.async.cg.shared.global [%0], [%1], 16;" :: "r"(dst), "l"(src));
}
#define CP_COMMIT() asm volatile("cp.async.commit_group;" ::: "memory")
#define CP_WAIT(n)  asm volatile("cp.async.wait_group %0;" :: "n"(n) : "memory")

__device__ __forceinline__ uint32_t pack_h2(float x, float y) {
    __half2 h = __floats2half2_rn(x, y);
    return *(uint32_t*)&h;
}
__device__ __forceinline__ float ex2(float x) {
    float r; asm("ex2.approx.ftz.f32 %0, %1;" : "=f"(r) : "f"(x)); return r;
}

// ---------------- merged fp32 -> fp16 convert --------------------------------
__global__ void __launch_bounds__(256) cvt_all(
    const float* __restrict__ x,  const float* __restrict__ Wq,
    const float* __restrict__ Wk, const float* __restrict__ Wv,
    const float* __restrict__ Wproj, __half* __restrict__ xo, int nx4)
{
    int i = blockIdx.x * 256 + threadIdx.x;
    const float* src;
    __half* h;
    int o;
    if (i < nx4) { src = x; h = xo; o = i; }
    else {
        i -= nx4;
        if      (i < 262144)  { src = Wq;    h = g_w;           o = i; }
        else if (i < 327680)  { src = Wk;    h = g_w + 1048576; o = i - 262144; }
        else if (i < 393216)  { src = Wv;    h = g_w + 1310720; o = i - 327680; }
        else if (i < 655360)  { src = Wproj; h = g_wp;          o = i - 393216; }
        else return;
    }
    float4 v = ((const float4*)src)[o];
    ((uint32_t*)h)[o*2]   = pack_h2(v.x, v.y);
    ((uint32_t*)h)[o*2+1] = pack_h2(v.z, v.w);
}

#define STG_BYTES 32768   /* A|B regions, 16KB each */
#define GSMEM (3*STG_BYTES)

// ================= variant A: proj GEMM, 128 thr, warp tile 64x64 ===========
__device__ __forceinline__ void gemm_issue_stage128(
    uint32_t sbase, int stg, int kc,
    const __half* __restrict__ A, const __half* __restrict__ W,
    int bm, int bn, int K, int tid)
{
    #pragma unroll
    for (int i = 0; i < 16; i++) {
        const int idx = i * 128 + tid;           // 0..2047
        const int region = idx >> 10;            // 0:A 1:W
        const int cid = idx & 1023;
        const int row = cid >> 3, c16 = cid & 7;
        const uint32_t off = row * 128 + c16 * 16;
        const uint32_t sw = off ^ ((off >> 3) & 0x70);
        const int gk = kc * 64 + c16 * 8;
        const __half* src = region ? (W + (size_t)(bn + row) * K + gk)
                                   : (A + (size_t)(bm + row) * K + gk);
        cp16(sbase + stg * STG_BYTES + region * 16384 + sw, src);
    }
}

__global__ void __launch_bounds__(128, 2) gemm_mma(
    const __half* __restrict__ A, const __half* __restrict__ W,
    float* __restrict__ C, int ldc)
{
    constexpr int K = 1024;
    constexpr int NK = K / 64;
    extern __shared__ char gsm[];
    const uint32_t sbase = smem_to_u32(gsm);
    const int tid = threadIdx.x, wid = tid >> 5, lane = tid & 31;
    const int warpM = wid & 1, warpN = wid >> 1;
    const int rIn = lane & 7, mId = lane >> 3;
    const int bm = blockIdx.y * 128, bn = blockIdx.x * 128;

    float c[4][8][4];
    #pragma unroll
    for (int mt = 0; mt < 4; mt++)
        #pragma unroll
        for (int n = 0; n < 8; n++)
            #pragma unroll
            for (int j = 0; j < 4; j++) c[mt][n][j] = 0.f;

    gemm_issue_stage128(sbase, 0, 0, A, W, bm, bn, K, tid); CP_COMMIT();
    gemm_issue_stage128(sbase, 1, 1, A, W, bm, bn, K, tid); CP_COMMIT();

    for (int kc = 0; kc < NK; kc++) {
        const int stg = kc % 3;
        if (kc + 2 < NK) {
            gemm_issue_stage128(sbase, (kc + 2) % 3, kc + 2, A, W, bm, bn, K, tid);
            CP_COMMIT();
            CP_WAIT(2);
        } else if (kc + 1 < NK) {
            CP_WAIT(1);
        } else {
            CP_WAIT(0);
        }
        __syncthreads();

        const uint32_t aA = sbase + stg * STG_BYTES;
        const uint32_t aB = aA + 16384;

        #pragma unroll
        for (int kk = 0; kk < 64; kk += 16) {
            uint32_t a[4][4];
            #pragma unroll
            for (int mt = 0; mt < 4; mt++) {
                const int row = warpM * 64 + mt * 16 + (mId & 1) * 8 + rIn;
                const int colB = (kk + (mId >> 1) * 8) * 2;
                const uint32_t off = row * 128 + colB;
                const uint32_t sw = off ^ ((off >> 3) & 0x70);
                ldsm_x4(a[mt][0], a[mt][1], a[mt][2], a[mt][3], aA + sw);
            }
            uint32_t b[8][2];
            #pragma unroll
            for (int nt = 0; nt < 4; nt++) {
                const int row = warpN * 64 + nt * 16 + (mId >> 1) * 8 + rIn;
                const int colB = (kk + (mId & 1) * 8) * 2;
                const uint32_t off = row * 128 + colB;
                const uint32_t sw = off ^ ((off >> 3) & 0x70);
                ldsm_x4(b[2*nt][0], b[2*nt][1], b[2*nt+1][0], b[2*nt+1][1], aB + sw);
            }
            #pragma unroll
            for (int mt = 0; mt < 4; mt++)
                #pragma unroll
                for (int n = 0; n < 8; n++)
                    mma_f16(c[mt][n], a[mt], b[n]);
        }
        __syncthreads();
    }

    const int g = lane >> 2, t = lane & 3;
    #pragma unroll
    for (int mt = 0; mt < 4; mt++) {
        #pragma unroll
        for (int n = 0; n < 8; n++) {
            const int r0 = bm + warpM * 64 + mt * 16 + g;
            const int col = bn + warpN * 64 + n * 8 + t * 2;
            *(float2*)&C[(size_t)r0 * ldc + col]       = make_float2(c[mt][n][0], c[mt][n][1]);
            *(float2*)&C[(size_t)(r0 + 8) * ldc + col] = make_float2(c[mt][n][2], c[mt][n][3]);
        }
    }
}

// ================= variant B: QKV GEMM, 256 thr, warp tile 32x64 ============
__device__ __forceinline__ void gemm_issue_stage256(
    uint32_t sbase, int stg, int kc,
    const __half* __restrict__ A, const __half* __restrict__ W,
    int bm, int bn, int K, int tid)
{
    #pragma unroll
    for (int i = 0; i < 8; i++) {
        const int idx = i * 256 + tid;           // 0..2047
        const int region = idx >> 10;            // 0:A 1:W
        const int cid = idx & 1023;
        const int row = cid >> 3, c16 = cid & 7;
        const uint32_t off = row * 128 + c16 * 16;
        const uint32_t sw = off ^ ((off >> 3) & 0x70);
        const int gk = kc * 64 + c16 * 8;
        const __half* src = region ? (W + (size_t)(bn + row) * K + gk)
                                   : (A + (size_t)(bm + row) * K + gk);
        cp16(sbase + stg * STG_BYTES + region * 16384 + sw, src);
    }
}

__global__ void __launch_bounds__(256, 2) gemm_qkv(
    const __half* __restrict__ A, const __half* __restrict__ W,
    const float* __restrict__ x, const float* __restrict__ ve,
    const float* __restrict__ cosb, const float* __restrict__ sinb,
    const float* __restrict__ Wgate, int S)
{
    constexpr int K = 1024;
    constexpr int NK = K / 64;
    extern __shared__ char gsm[];
    const uint32_t sbase = smem_to_u32(gsm);
    const int tid = threadIdx.x, wid = tid >> 5, lane = tid & 31;
    const int warpM = wid & 3, warpN = wid >> 2;
    const int rIn = lane & 7, mId = lane >> 3;
    const int bm = blockIdx.y * 128, bn = blockIdx.x * 128;

    float c[2][8][4];
    #pragma unroll
    for (int mt = 0; mt < 2; mt++)
        #pragma unroll
        for (int n = 0; n < 8; n++)
            #pragma unroll
            for (int j = 0; j < 4; j++) c[mt][n][j] = 0.f;

    gemm_issue_stage256(sbase, 0, 0, A, W, bm, bn, K, tid); CP_COMMIT();
    gemm_issue_stage256(sbase, 1, 1, A, W, bm, bn, K, tid); CP_COMMIT();

    for (int kc = 0; kc < NK; kc++) {
        const int stg = kc % 3;
        if (kc + 2 < NK) {
            gemm_issue_stage256(sbase, (kc + 2) % 3, kc + 2, A, W, bm, bn, K, tid);
            CP_COMMIT();
            CP_WAIT(2);
        } else if (kc + 1 < NK) {
            CP_WAIT(1);
        } else {
            CP_WAIT(0);
        }
        __syncthreads();

        const uint32_t aA = sbase + stg * STG_BYTES;
        const uint32_t aB = aA + 16384;

        #pragma unroll
        for (int kk = 0; kk < 64; kk += 16) {
            uint32_t a[2][4];
            #pragma unroll
            for (int mt = 0; mt < 2; mt++) {
                const int row = warpM * 32 + mt * 16 + (mId & 1) * 8 + rIn;
                const int colB = (kk + (mId >> 1) * 8) * 2;
                const uint32_t off = row * 128 + colB;
                const uint32_t sw = off ^ ((off >> 3) & 0x70);
                ldsm_x4(a[mt][0], a[mt][1], a[mt][2], a[mt][3], aA + sw);
            }
            uint32_t b[8][2];
            #pragma unroll
            for (int nt = 0; nt < 4; nt++) {
                const int row = warpN * 64 + nt * 16 + (mId >> 1) * 8 + rIn;
                const int colB = (kk + (mId & 1) * 8) * 2;
                const uint32_t off = row * 128 + colB;
                const uint32_t sw = off ^ ((off >> 3) & 0x70);
                ldsm_x4(b[2*nt][0], b[2*nt][1], b[2*nt+1][0], b[2*nt+1][1], aB + sw);
            }
            #pragma unroll
            for (int mt = 0; mt < 2; mt++)
                #pragma unroll
                for (int n = 0; n < 8; n++)
                    mma_f16(c[mt][n], a[mt], b[n]);
        }
        __syncthreads();
    }

    const int g = lane >> 2, t = lane & 3;
    const int colbase = bn + warpN * 64;
    const int type = (colbase < 1024) ? 0 : (colbase < 1280 ? 1 : 2);
    // q gets softmax scale and log2(e) folded in; k gets plain 1.2
    const float sQK = (type == 0) ? (1.2f * 0.125f * 1.44269504f) : 1.2f;

    #pragma unroll
    for (int mt = 0; mt < 2; mt++) {
        #pragma unroll
        for (int e = 0; e < 2; e++) {
            const int row = warpM * 32 + mt * 16 + g + e * 8;
            const int m = bm + row;
            const int b = m / S, s = m - b * S;
            if (type <= 1) {
                float r1[4][2], r2[4][2];
                float ss = 0.f;
                #pragma unroll
                for (int n = 0; n < 4; n++) {
                    const int d0 = n * 8 + 2 * t;
                    const float cs0 = cosb[s*32 + d0], cs1 = cosb[s*32 + d0 + 1];
                    const float sn0 = sinb[s*32 + d0], sn1 = sinb[s*32 + d0 + 1];
                    const float t1a = c[mt][n][2*e],   t1b = c[mt][n][2*e+1];
                    const float t2a = c[mt][n+4][2*e], t2b = c[mt][n+4][2*e+1];
                    r1[n][0] = t1a*cs0 + t2a*sn0;  r1[n][1] = t1b*cs1 + t2b*sn1;
                    r2[n][0] = t2a*cs0 - t1a*sn0;  r2[n][1] = t2b*cs1 - t1b*sn1;
                    ss += r1[n][0]*r1[n][0] + r1[n][1]*r1[n][1]
                        + r2[n][0]*r2[n][0] + r2[n][1]*r2[n][1];
                }
                ss += __shfl_xor_sync(0xffffffffu, ss, 1);
                ss += __shfl_xor_sync(0xffffffffu, ss, 2);
                const float inv = rsqrtf(ss * (1.0f/64.0f) + RMS_EPS) * sQK;
                __half* dst;
                size_t doff;
                if (type == 0) {
                    const int hh = colbase >> 6;
                    doff = ((size_t)(b*NH + hh)*S + s) * HD;
                    dst = g_q;
                } else {
                    const int kh = (colbase - 1024) >> 6;
                    doff = ((size_t)(b*NKV + kh)*S + s) * HD;
                    dst = g_k;
                }
                #pragma unroll
                for (int n = 0; n < 4; n++) {
                    const int d0 = n * 8 + 2 * t;
                    *(uint32_t*)(dst + doff + d0)      = pack_h2(r1[n][0]*inv, r1[n][1]*inv);
                    *(uint32_t*)(dst + doff + d0 + 32) = pack_h2(r2[n][0]*inv, r2[n][1]*inv);
                }
            } else {
                const int kvh = (colbase - 1280) >> 6;
                float gz = 0.f;
                #pragma unroll
                for (int j = 0; j < 3; j++)
                    gz += x[(size_t)m*NE + 3*t + j] * Wgate[kvh*12 + 3*t + j];
                gz += __shfl_xor_sync(0xffffffffu, gz, 1);
                gz += __shfl_xor_sync(0xffffffffu, gz, 2);
                const float gate = 3.0f / (1.0f + __expf(-gz));
                const size_t doff = ((size_t)(b*NKV + kvh)*S + s) * HD;
                const float* vep = ve + (size_t)m*256 + kvh*64;
                #pragma unroll
                for (int n = 0; n < 8; n++) {
                    const int d0 = n * 8 + 2 * t;
                    const float v0 = c[mt][n][2*e]   + gate * vep[d0];
                    const float v1 = c[mt][n][2*e+1] + gate * vep[d0+1];
                    *(uint32_t*)(g_v + doff + d0) = pack_h2(v0, v1);
                }
            }
        }
    }
}

// ---------------- flash attention, fixed-shift softmax (round-7 exact) -------
#define AOFF_Q   0
#define AOFF_STG 8192
#define ASTG_STRIDE 16640   /* K (8KB) + V (8KB) + amask (256B) */
#define ASMEM (AOFF_STG + 2*ASTG_STRIDE)

__device__ __forceinline__ void attn_issue_stage(
    uint32_t sbase, int buf,
    const __half* K, const __half* V, const int* amrow, int tid)
{
    const uint32_t stg = sbase + AOFF_STG + buf * ASTG_STRIDE;
    #pragma unroll
    for (int i = 0; i < 8; i++) {
        const int idx = i * 128 + tid;        // 0..1023
        const int region = idx >> 9;          // 0:K 1:V
        const int cid = idx & 511;
        const int row = cid >> 3, c16 = cid & 7;
        const uint32_t off = row * 128 + c16 * 16;
        const uint32_t sw = off ^ ((off >> 3) & 0x70);
        const __half* src = region ? (V + row * 64 + c16 * 8) : (K + row * 64 + c16 * 8);
        cp16(stg + region * 8192 + sw, src);
    }
    if (tid < 16) cp16(stg + 16384 + tid * 16, amrow + tid * 4);
}

__global__ void __launch_bounds__(128) attn_kernel(
    const int* __restrict__ amask, const int* __restrict__ lwp, int S)
{
    extern __shared__ char asm_[];
    const uint32_t sbase = smem_to_u32(asm_);
    const int q0 = blockIdx.x * 64;
    const int h  = blockIdx.y;
    const int bz = blockIdx.z;
    const int kvh = h >> 2;
    const int LW = *lwp;
    const int tid = threadIdx.x, warp = tid >> 5, lane = tid & 31;
    const int rIn = lane & 7, mId = lane >> 3;
    const int g = lane >> 2, t = lane & 3;

    const __half* Q0 = g_q + ((size_t)(bz*NH + h)*S + q0) * HD;
    const __half* K0 = g_k + ((size_t)(bz*NKV + kvh)*S) * HD;
    const __half* V0 = g_v + ((size_t)(bz*NKV + kvh)*S) * HD;
    const int* am0 = amask + bz * S;

    #pragma unroll
    for (int i = 0; i < 4; i++) {
        const int idx = i * 128 + tid;
        const int row = idx >> 3, c16 = idx & 7;
        const uint32_t off = row * 128 + c16 * 16;
        const uint32_t sw = off ^ ((off >> 3) & 0x70);
        *(uint4*)(asm_ + AOFF_Q + sw) = *(const uint4*)(Q0 + row * 64 + c16 * 8);
    }

    int kmin = q0 - LW + 1; if (kmin < 0) kmin = 0;
    const int kt0 = kmin >> 6, kt1 = q0 >> 6;
    const int nt = kt1 - kt0 + 1;

    attn_issue_stage(sbase, 0, K0 + (size_t)(kt0<<6)*HD, V0 + (size_t)(kt0<<6)*HD,
                     am0 + (kt0<<6), tid);
    CP_COMMIT();
    if (nt > 1) {
        attn_issue_stage(sbase, 1, K0 + (size_t)((kt0+1)<<6)*HD, V0 + (size_t)((kt0+1)<<6)*HD,
                         am0 + ((kt0+1)<<6), tid);
        CP_COMMIT();
    }

    __syncthreads();

    uint32_t aq[4][4];
    #pragma unroll
    for (int kk = 0; kk < 4; kk++) {
        const int row = warp * 16 + (mId & 1) * 8 + rIn;
        const int colB = (kk * 16 + (mId >> 1) * 8) * 2;
        const uint32_t off = row * 128 + colB;
        const uint32_t sw = off ^ ((off >> 3) & 0x70);
        ldsm_x4(aq[kk][0], aq[kk][1], aq[kk][2], aq[kk][3], sbase + AOFF_Q + sw);
    }

    float o[8][4];
    #pragma unroll
    for (int j = 0; j < 8; j++)
        #pragma unroll
        for (int e = 0; e < 4; e++) o[j][e] = 0.f;
    float l0 = 0.f, l1 = 0.f;
    const int r0g = q0 + warp * 16 + g;
    const int r1g = r0g + 8;

    for (int i = 0; i < nt; i++) {
        const int kt = kt0 + i, buf = i & 1;
        const int k0 = kt << 6;
        if (i + 1 < nt) { CP_WAIT(1); } else { CP_WAIT(0); }
        __syncthreads();

        const uint32_t stg = sbase + AOFF_STG + buf * ASTG_STRIDE;
        const uint32_t sK = stg, sV = stg + 8192;
        const int* sAm = (const int*)(asm_ + AOFF_STG + buf * ASTG_STRIDE + 16384);

        float sc[8][4];
        #pragma unroll
        for (int j = 0; j < 8; j++)
            #pragma unroll
            for (int e = 0; e < 4; e++) sc[j][e] = 0.f;

        #pragma unroll
        for (int kk = 0; kk < 4; kk++) {
            uint32_t b[8][2];
            #pragma unroll
            for (int ntp = 0; ntp < 4; ntp++) {
                const int row = ntp * 16 + (mId >> 1) * 8 + rIn;
                const int colB = (kk * 16 + (mId & 1) * 8) * 2;
                const uint32_t off = row * 128 + colB;
                const uint32_t sw = off ^ ((off >> 3) & 0x70);
                ldsm_x4(b[2*ntp][0], b[2*ntp][1], b[2*ntp+1][0], b[2*ntp+1][1], sK + sw);
            }
            #pragma unroll
            for (int j = 0; j < 8; j++)
                mma_f16(sc[j], aq[kk], b[j]);
        }

        // fixed-shift softmax: p = 2^(s - SHIFT), masked -> 0.
        #pragma unroll
        for (int j = 0; j < 8; j++) {
            const int ce = 8*j + 2*t, co = ce + 1;
            const int ae = sAm[ce], ao = sAm[co];
            const int gce = k0 + ce, gco = k0 + co;
            const bool a0 = ((unsigned)(r0g - gce) < (unsigned)LW) && (ae != 0);
            const bool a1 = ((unsigned)(r0g - gco) < (unsigned)LW) && (ao != 0);
            const bool a2 = ((unsigned)(r1g - gce) < (unsigned)LW) && (ae != 0);
            const bool a3 = ((unsigned)(r1g - gco) < (unsigned)LW) && (ao != 0);
            const float p0 = a0 ? ex2(sc[j][0] - SM_SHIFT) : 0.f;
            const float p1 = a1 ? ex2(sc[j][1] - SM_SHIFT) : 0.f;
            const float p2 = a2 ? ex2(sc[j][2] - SM_SHIFT) : 0.f;
            const float p3 = a3 ? ex2(sc[j][3] - SM_SHIFT) : 0.f;
            sc[j][0] = p0; sc[j][1] = p1; sc[j][2] = p2; sc[j][3] = p3;
            l0 += p0 + p1; l1 += p2 + p3;
        }

        uint32_t pa[4][4];
        #pragma unroll
        for (int kb = 0; kb < 4; kb++) {
            const int j0 = 2*kb, j1 = 2*kb + 1;
            pa[kb][0] = pack_h2(sc[j0][0], sc[j0][1]);
            pa[kb][1] = pack_h2(sc[j0][2], sc[j0][3]);
            pa[kb][2] = pack_h2(sc[j1][0], sc[j1][1]);
            pa[kb][3] = pack_h2(sc[j1][2], sc[j1][3]);
        }

        #pragma unroll
        for (int kb = 0; kb < 4; kb++) {
            uint32_t v[8][2];
            #pragma unroll
            for (int dp = 0; dp < 4; dp++) {
                const int row = kb * 16 + (mId & 1) * 8 + rIn;
                const int colB = (dp * 16 + (mId >> 1) * 8) * 2;
                const uint32_t off = row * 128 + colB;
                const uint32_t sw = off ^ ((off >> 3) & 0x70);
                ldsm_x4_t(v[2*dp][0], v[2*dp][1], v[2*dp+1][0], v[2*dp+1][1], sV + sw);
            }
            #pragma unroll
            for (int j = 0; j < 8; j++)
                mma_f16(o[j], pa[kb], v[j]);
        }

        __syncthreads();
        if (i + 2 < nt) {
            const int kn = (kt + 2) << 6;
            attn_issue_stage(sbase, buf, K0 + (size_t)kn*HD, V0 + (size_t)kn*HD,
                             am0 + kn, tid);
            CP_COMMIT();
        }
    }

    l0 += __shfl_xor_sync(0xffffffffu, l0, 1);
    l0 += __shfl_xor_sync(0xffffffffu, l0, 2);
    l1 += __shfl_xor_sync(0xffffffffu, l1, 1);
    l1 += __shfl_xor_sync(0xffffffffu, l1, 2);

    const float inv0 = 1.0f / l0, inv1 = 1.0f / l1;
    const size_t tok0 = (size_t)(bz*S + r0g) * NE + h*HD;
    const size_t tok1 = (size_t)(bz*S + r1g) * NE + h*HD;
    #pragma unroll
    for (int j = 0; j < 8; j++) {
        const int d0 = 8*j + 2*t;
        *(uint32_t*)(g_y + tok0 + d0) = pack_h2(o[j][0]*inv0, o[j][1]*inv0);
        *(uint32_t*)(g_y + tok1 + d0) = pack_h2(o[j][2]*inv1, o[j][3]*inv1);
    }
}

// ---------------- launch ----------------------------------------------------
extern "C" void kernel_launch(void* const* d_in, const int* in_sizes, int n_in,
                              void* d_out, int out_size)
{
    const float* x     = (const float*)d_in[0];
    const float* ve    = (const float*)d_in[1];
    const float* cosb  = (const float*)d_in[2];
    const float* sinb  = (const float*)d_in[3];
    const float* Wq    = (const float*)d_in[4];
    const float* Wk    = (const float*)d_in[5];
    const float* Wv    = (const float*)d_in[6];
    const float* Wproj = (const float*)d_in[7];
    const float* Wgate = (const float*)d_in[8];
    const int*   amask = (const int*)d_in[9];
    const int*   lw    = (const int*)d_in[10];
    float* out = (float*)d_out;

    const int S = in_sizes[2] / 32;        // cos is (S,1,32)
    const int B = in_sizes[0] / (S * NE);
    const int M = B * S;

    __half *xp, *wp, *wpp, *yp;
    cudaGetSymbolAddress((void**)&xp,  g_x);
    cudaGetSymbolAddress((void**)&wp,  g_w);
    cudaGetSymbolAddress((void**)&wpp, g_wp);
    cudaGetSymbolAddress((void**)&yp,  g_y);

    // merged fp32 -> fp16 converts
    const int nx4 = M * NE / 4;
    const int ntot = nx4 + 655360;
    cvt_all<<<(ntot + 255)/256, 256>>>(x, Wq, Wk, Wv, Wproj, xp, nx4);

    cudaFuncSetAttribute(gemm_qkv, cudaFuncAttributeMaxDynamicSharedMemorySize, GSMEM);
    cudaFuncSetAttribute(gemm_mma, cudaFuncAttributeMaxDynamicSharedMemorySize, GSMEM);

    // fused QKV projection + rope/rmsnorm/gate epilogue (32x64 warp tile)
    gemm_qkv<<<dim3(12, M/128), 256, GSMEM>>>(xp, wp, x, ve, cosb, sinb, Wgate, S);

    // attention (tensor-core flash, fixed-shift softmax)
    cudaFuncSetAttribute(attn_kernel, cudaFuncAttributeMaxDynamicSharedMemorySize, ASMEM);
    attn_kernel<<<dim3(S/64, NH, B), 128, ASMEM>>>(amask, lw, S);

    // output projection (64x64 warp tile) straight into d_out
    gemm_mma<<<dim3(8, M/128), 128, GSMEM>>>(yp, wpp, out, 1024);
}

// round 12
// speedup vs baseline: 1.1590x; 1.0261x over previous
#include <cuda_runtime.h>
#include <cuda_fp16.h>
#include <math.h>
#include <stdint.h>

#define NE   1024
#define NH   16
#define NKV  4
#define HD   64
#define SMAX 2048
#define BMAX 2
#define MMAX (BMAX*SMAX)
#define RMS_EPS 1.1920929e-07f
#define SM_SHIFT 13.0f

// ---------------- scratch (device globals; no allocation allowed) ----------
__device__ __half g_x[(size_t)MMAX*NE];          // x fp16
__device__ __half g_w[1536*1024];                // fused Wq|Wk|Wv fp16
__device__ __half g_wp[1024*1024];               // Wproj fp16
__device__ __half g_y[(size_t)MMAX*NE];          // attention out fp16
__device__ __half g_q[(size_t)BMAX*NH*SMAX*HD];  // roped q (scale+log2e folded)
__device__ __half g_k[(size_t)BMAX*NKV*SMAX*HD];
__device__ __half g_v[(size_t)BMAX*NKV*SMAX*HD];

// ---------------- PTX helpers (family-generic only) -------------------------
__device__ __forceinline__ uint32_t smem_to_u32(const void* p) {
    uint32_t a;
    asm("{ .reg .u64 t; cvta.to.shared.u64 t, %1; cvt.u32.u64 %0, t; }" : "=r"(a) : "l"(p));
    return a;
}
__device__ __forceinline__ void ldsm_x4(uint32_t& r0, uint32_t& r1, uint32_t& r2,
                                        uint32_t& r3, uint32_t addr) {
    asm volatile("ldmatrix.sync.aligned.m8n8.x4.shared.b16 {%0,%1,%2,%3}, [%4];"
        : "=r"(r0), "=r"(r1), "=r"(r2), "=r"(r3) : "r"(addr));
}
__device__ __forceinline__ void ldsm_x4_t(uint32_t& r0, uint32_t& r1, uint32_t& r2,
                                          uint32_t& r3, uint32_t addr) {
    asm volatile("ldmatrix.sync.aligned.m8n8.x4.trans.shared.b16 {%0,%1,%2,%3}, [%4];"
        : "=r"(r0), "=r"(r1), "=r"(r2), "=r"(r3) : "r"(addr));
}
__device__ __forceinline__ void mma_f16(float* c, const uint32_t* a, const uint32_t* b) {
    asm volatile("mma.sync.aligned.m16n8k16.row.col.f32.f16.f16.f32 "
        "{%0,%1,%2,%3}, {%4,%5,%6,%7}, {%8,%9}, {%0,%1,%2,%3};"
        : "+f"(c[0]), "+f"(c[1]), "+f"(c[2]), "+f"(c[3])
        : "r"(a[0]), "r"(a[1]), "r"(a[2]), "r"(a[3]), "r"(b[0]), "r"(b[1]));
}
__device__ __forceinline__ void cp16(uint32_t dst, const void* src) {
    asm volatile("cp.async.cg.shared.global [%0], [%1], 16;" :: "r"(dst), "l"(src));
}
#define CP_COMMIT() asm volatile("cp.async.commit_group;" ::: "memory")
#define CP_WAIT(n)  asm volatile("cp.async.wait_group %0;" :: "n"(n) : "memory")

__device__ __forceinline__ uint32_t pack_h2(float x, float y) {
    __half2 h = __floats2half2_rn(x, y);
    return *(uint32_t*)&h;
}
__device__ __forceinline__ float ex2(float x) {
    float r; asm("ex2.approx.ftz.f32 %0, %1;" : "=f"(r) : "f"(x)); return r;
}

// ---------------- merged fp32 -> fp16 convert --------------------------------
__global__ void __launch_bounds__(256) cvt_all(
    const float* __restrict__ x,  const float* __restrict__ Wq,
    const float* __restrict__ Wk, const float* __restrict__ Wv,
    const float* __restrict__ Wproj, __half* __restrict__ xo, int nx4)
{
    int i = blockIdx.x * 256 + threadIdx.x;
    const float* src;
    __half* h;
    int o;
    if (i < nx4) { src = x; h = xo; o = i; }
    else {
        i -= nx4;
        if      (i < 262144)  { src = Wq;    h = g_w;           o = i; }
        else if (i < 327680)  { src = Wk;    h = g_w + 1048576; o = i - 262144; }
        else if (i < 393216)  { src = Wv;    h = g_w + 1310720; o = i - 327680; }
        else if (i < 655360)  { src = Wproj; h = g_wp;          o = i - 393216; }
        else return;
    }
    float4 v = ((const float4*)src)[o];
    ((uint32_t*)h)[o*2]   = pack_h2(v.x, v.y);
    ((uint32_t*)h)[o*2+1] = pack_h2(v.z, v.w);
}

#define STG_BYTES 32768   /* A|B regions, 16KB each */
#define GSMEM (3*STG_BYTES)

// ================= variant A: proj GEMM, 128 thr, warp tile 64x64 ===========
__device__ __forceinline__ void gemm_issue_stage128(
    uint32_t sbase, int stg, int kc,
    const __half* __restrict__ A, const __half* __restrict__ W,
    int bm, int bn, int K, int tid)
{
    #pragma unroll
    for (int i = 0; i < 16; i++) {
        const int idx = i * 128 + tid;           // 0..2047
        const int region = idx >> 10;            // 0:A 1:W
        const int cid = idx & 1023;
        const int row = cid >> 3, c16 = cid & 7;
        const uint32_t off = row * 128 + c16 * 16;
        const uint32_t sw = off ^ ((off >> 3) & 0x70);
        const int gk = kc * 64 + c16 * 8;
        const __half* src = region ? (W + (size_t)(bn + row) * K + gk)
                                   : (A + (size_t)(bm + row) * K + gk);
        cp16(sbase + stg * STG_BYTES + region * 16384 + sw, src);
    }
}

__global__ void __launch_bounds__(128, 2) gemm_mma(
    const __half* __restrict__ A, const __half* __restrict__ W,
    float* __restrict__ C, int ldc)
{
    constexpr int K = 1024;
    constexpr int NK = K / 64;
    extern __shared__ char gsm[];
    const uint32_t sbase = smem_to_u32(gsm);
    const int tid = threadIdx.x, wid = tid >> 5, lane = tid & 31;
    const int warpM = wid & 1, warpN = wid >> 1;
    const int rIn = lane & 7, mId = lane >> 3;
    const int bm = blockIdx.y * 128, bn = blockIdx.x * 128;

    float c[4][8][4];
    #pragma unroll
    for (int mt = 0; mt < 4; mt++)
        #pragma unroll
        for (int n = 0; n < 8; n++)
            #pragma unroll
            for (int j = 0; j < 4; j++) c[mt][n][j] = 0.f;

    gemm_issue_stage128(sbase, 0, 0, A, W, bm, bn, K, tid); CP_COMMIT();
    gemm_issue_stage128(sbase, 1, 1, A, W, bm, bn, K, tid); CP_COMMIT();

    for (int kc = 0; kc < NK; kc++) {
        const int stg = kc % 3;
        if (kc + 2 < NK) {
            gemm_issue_stage128(sbase, (kc + 2) % 3, kc + 2, A, W, bm, bn, K, tid);
            CP_COMMIT();
            CP_WAIT(2);
        } else if (kc + 1 < NK) {
            CP_WAIT(1);
        } else {
            CP_WAIT(0);
        }
        __syncthreads();

        const uint32_t aA = sbase + stg * STG_BYTES;
        const uint32_t aB = aA + 16384;

        #pragma unroll
        for (int kk = 0; kk < 64; kk += 16) {
            uint32_t a[4][4];
            #pragma unroll
            for (int mt = 0; mt < 4; mt++) {
                const int row = warpM * 64 + mt * 16 + (mId & 1) * 8 + rIn;
                const int colB = (kk + (mId >> 1) * 8) * 2;
                const uint32_t off = row * 128 + colB;
                const uint32_t sw = off ^ ((off >> 3) & 0x70);
                ldsm_x4(a[mt][0], a[mt][1], a[mt][2], a[mt][3], aA + sw);
            }
            uint32_t b[8][2];
            #pragma unroll
            for (int nt = 0; nt < 4; nt++) {
                const int row = warpN * 64 + nt * 16 + (mId >> 1) * 8 + rIn;
                const int colB = (kk + (mId & 1) * 8) * 2;
                const uint32_t off = row * 128 + colB;
                const uint32_t sw = off ^ ((off >> 3) & 0x70);
                ldsm_x4(b[2*nt][0], b[2*nt][1], b[2*nt+1][0], b[2*nt+1][1], aB + sw);
            }
            #pragma unroll
            for (int mt = 0; mt < 4; mt++)
                #pragma unroll
                for (int n = 0; n < 8; n++)
                    mma_f16(c[mt][n], a[mt], b[n]);
        }
        __syncthreads();
    }

    const int g = lane >> 2, t = lane & 3;
    #pragma unroll
    for (int mt = 0; mt < 4; mt++) {
        #pragma unroll
        for (int n = 0; n < 8; n++) {
            const int r0 = bm + warpM * 64 + mt * 16 + g;
            const int col = bn + warpN * 64 + n * 8 + t * 2;
            *(float2*)&C[(size_t)r0 * ldc + col]       = make_float2(c[mt][n][0], c[mt][n][1]);
            *(float2*)&C[(size_t)(r0 + 8) * ldc + col] = make_float2(c[mt][n][2], c[mt][n][3]);
        }
    }
}

// ================= variant B: QKV GEMM, 256 thr, warp tile 32x64 ============
__device__ __forceinline__ void gemm_issue_stage256(
    uint32_t sbase, int stg, int kc,
    const __half* __restrict__ A, const __half* __restrict__ W,
    int bm, int bn, int K, int tid)
{
    #pragma unroll
    for (int i = 0; i < 8; i++) {
        const int idx = i * 256 + tid;           // 0..2047
        const int region = idx >> 10;            // 0:A 1:W
        const int cid = idx & 1023;
        const int row = cid >> 3, c16 = cid & 7;
        const uint32_t off = row * 128 + c16 * 16;
        const uint32_t sw = off ^ ((off >> 3) & 0x70);
        const int gk = kc * 64 + c16 * 8;
        const __half* src = region ? (W + (size_t)(bn + row) * K + gk)
                                   : (A + (size_t)(bm + row) * K + gk);
        cp16(sbase + stg * STG_BYTES + region * 16384 + sw, src);
    }
}

__global__ void __launch_bounds__(256, 2) gemm_qkv(
    const __half* __restrict__ A, const __half* __restrict__ W,
    const float* __restrict__ x, const float* __restrict__ ve,
    const float* __restrict__ cosb, const float* __restrict__ sinb,
    const float* __restrict__ Wgate, int S)
{
    constexpr int K = 1024;
    constexpr int NK = K / 64;
    extern __shared__ char gsm[];
    const uint32_t sbase = smem_to_u32(gsm);
    const int tid = threadIdx.x, wid = tid >> 5, lane = tid & 31;
    const int warpM = wid & 3, warpN = wid >> 2;
    const int rIn = lane & 7, mId = lane >> 3;
    const int bm = blockIdx.y * 128, bn = blockIdx.x * 128;

    float c[2][8][4];
    #pragma unroll
    for (int mt = 0; mt < 2; mt++)
        #pragma unroll
        for (int n = 0; n < 8; n++)
            #pragma unroll
            for (int j = 0; j < 4; j++) c[mt][n][j] = 0.f;

    gemm_issue_stage256(sbase, 0, 0, A, W, bm, bn, K, tid); CP_COMMIT();
    gemm_issue_stage256(sbase, 1, 1, A, W, bm, bn, K, tid); CP_COMMIT();

    for (int kc = 0; kc < NK; kc++) {
        const int stg = kc % 3;
        if (kc + 2 < NK) {
            gemm_issue_stage256(sbase, (kc + 2) % 3, kc + 2, A, W, bm, bn, K, tid);
            CP_COMMIT();
            CP_WAIT(2);
        } else if (kc + 1 < NK) {
            CP_WAIT(1);
        } else {
            CP_WAIT(0);
        }
        __syncthreads();

        const uint32_t aA = sbase + stg * STG_BYTES;
        const uint32_t aB = aA + 16384;

        #pragma unroll
        for (int kk = 0; kk < 64; kk += 16) {
            uint32_t a[2][4];
            #pragma unroll
            for (int mt = 0; mt < 2; mt++) {
                const int row = warpM * 32 + mt * 16 + (mId & 1) * 8 + rIn;
                const int colB = (kk + (mId >> 1) * 8) * 2;
                const uint32_t off = row * 128 + colB;
                const uint32_t sw = off ^ ((off >> 3) & 0x70);
                ldsm_x4(a[mt][0], a[mt][1], a[mt][2], a[mt][3], aA + sw);
            }
            uint32_t b[8][2];
            #pragma unroll
            for (int nt = 0; nt < 4; nt++) {
                const int row = warpN * 64 + nt * 16 + (mId >> 1) * 8 + rIn;
                const int colB = (kk + (mId & 1) * 8) * 2;
                const uint32_t off = row * 128 + colB;
                const uint32_t sw = off ^ ((off >> 3) & 0x70);
                ldsm_x4(b[2*nt][0], b[2*nt][1], b[2*nt+1][0], b[2*nt+1][1], aB + sw);
            }
            #pragma unroll
            for (int mt = 0; mt < 2; mt++)
                #pragma unroll
                for (int n = 0; n < 8; n++)
                    mma_f16(c[mt][n], a[mt], b[n]);
        }
        __syncthreads();
    }

    const int g = lane >> 2, t = lane & 3;
    const int colbase = bn + warpN * 64;
    const int type = (colbase < 1024) ? 0 : (colbase < 1280 ? 1 : 2);
    // q gets softmax scale and log2(e) folded in; k gets plain 1.2
    const float sQK = (type == 0) ? (1.2f * 0.125f * 1.44269504f) : 1.2f;

    #pragma unroll
    for (int mt = 0; mt < 2; mt++) {
        #pragma unroll
        for (int e = 0; e < 2; e++) {
            const int row = warpM * 32 + mt * 16 + g + e * 8;
            const int m = bm + row;
            const int b = m / S, s = m - b * S;
            if (type <= 1) {
                float r1[4][2], r2[4][2];
                float ss = 0.f;
                #pragma unroll
                for (int n = 0; n < 4; n++) {
                    const int d0 = n * 8 + 2 * t;
                    const float cs0 = cosb[s*32 + d0], cs1 = cosb[s*32 + d0 + 1];
                    const float sn0 = sinb[s*32 + d0], sn1 = sinb[s*32 + d0 + 1];
                    const float t1a = c[mt][n][2*e],   t1b = c[mt][n][2*e+1];
                    const float t2a = c[mt][n+4][2*e], t2b = c[mt][n+4][2*e+1];
                    r1[n][0] = t1a*cs0 + t2a*sn0;  r1[n][1] = t1b*cs1 + t2b*sn1;
                    r2[n][0] = t2a*cs0 - t1a*sn0;  r2[n][1] = t2b*cs1 - t1b*sn1;
                    ss += r1[n][0]*r1[n][0] + r1[n][1]*r1[n][1]
                        + r2[n][0]*r2[n][0] + r2[n][1]*r2[n][1];
                }
                ss += __shfl_xor_sync(0xffffffffu, ss, 1);
                ss += __shfl_xor_sync(0xffffffffu, ss, 2);
                const float inv = rsqrtf(ss * (1.0f/64.0f) + RMS_EPS) * sQK;
                __half* dst;
                size_t doff;
                if (type == 0) {
                    const int hh = colbase >> 6;
                    doff = ((size_t)(b*NH + hh)*S + s) * HD;
                    dst = g_q;
                } else {
                    const int kh = (colbase - 1024) >> 6;
                    doff = ((size_t)(b*NKV + kh)*S + s) * HD;
                    dst = g_k;
                }
                #pragma unroll
                for (int n = 0; n < 4; n++) {
                    const int d0 = n * 8 + 2 * t;
                    *(uint32_t*)(dst + doff + d0)      = pack_h2(r1[n][0]*inv, r1[n][1]*inv);
                    *(uint32_t*)(dst + doff + d0 + 32) = pack_h2(r2[n][0]*inv, r2[n][1]*inv);
                }
            } else {
                const int kvh = (colbase - 1280) >> 6;
                float gz = 0.f;
                #pragma unroll
                for (int j = 0; j < 3; j++)
                    gz += x[(size_t)m*NE + 3*t + j] * Wgate[kvh*12 + 3*t + j];
                gz += __shfl_xor_sync(0xffffffffu, gz, 1);
                gz += __shfl_xor_sync(0xffffffffu, gz, 2);
                const float gate = 3.0f / (1.0f + __expf(-gz));
                const size_t doff = ((size_t)(b*NKV + kvh)*S + s) * HD;
                const float* vep = ve + (size_t)m*256 + kvh*64;
                #pragma unroll
                for (int n = 0; n < 8; n++) {
                    const int d0 = n * 8 + 2 * t;
                    const float v0 = c[mt][n][2*e]   + gate * vep[d0];
                    const float v1 = c[mt][n][2*e+1] + gate * vep[d0+1];
                    *(uint32_t*)(g_v + doff + d0) = pack_h2(v0, v1);
                }
            }
        }
    }
}

// ---------------- flash attention, fixed-shift softmax + fast interior path --
#define AOFF_Q   0
#define AOFF_STG 8192
#define ASTG_STRIDE 16640   /* K (8KB) + V (8KB) + amask (256B) */
#define ASMEM (AOFF_STG + 2*ASTG_STRIDE)

__device__ __forceinline__ void attn_issue_stage(
    uint32_t sbase, int buf,
    const __half* K, const __half* V, const int* amrow, int tid)
{
    const uint32_t stg = sbase + AOFF_STG + buf * ASTG_STRIDE;
    #pragma unroll
    for (int i = 0; i < 8; i++) {
        const int idx = i * 128 + tid;        // 0..1023
        const int region = idx >> 9;          // 0:K 1:V
        const int cid = idx & 511;
        const int row = cid >> 3, c16 = cid & 7;
        const uint32_t off = row * 128 + c16 * 16;
        const uint32_t sw = off ^ ((off >> 3) & 0x70);
        const __half* src = region ? (V + row * 64 + c16 * 8) : (K + row * 64 + c16 * 8);
        cp16(stg + region * 8192 + sw, src);
    }
    if (tid < 16) cp16(stg + 16384 + tid * 16, amrow + tid * 4);
}

__global__ void __launch_bounds__(128) attn_kernel(
    const int* __restrict__ amask, const int* __restrict__ lwp, int S)
{
    extern __shared__ char asm_[];
    const uint32_t sbase = smem_to_u32(asm_);
    const int q0 = blockIdx.x * 64;
    const int h  = blockIdx.y;
    const int bz = blockIdx.z;
    const int kvh = h >> 2;
    const int LW = *lwp;
    const int tid = threadIdx.x, warp = tid >> 5, lane = tid & 31;
    const int rIn = lane & 7, mId = lane >> 3;
    const int g = lane >> 2, t = lane & 3;

    const __half* Q0 = g_q + ((size_t)(bz*NH + h)*S + q0) * HD;
    const __half* K0 = g_k + ((size_t)(bz*NKV + kvh)*S) * HD;
    const __half* V0 = g_v + ((size_t)(bz*NKV + kvh)*S) * HD;
    const int* am0 = amask + bz * S;

    #pragma unroll
    for (int i = 0; i < 4; i++) {
        const int idx = i * 128 + tid;
        const int row = idx >> 3, c16 = idx & 7;
        const uint32_t off = row * 128 + c16 * 16;
        const uint32_t sw = off ^ ((off >> 3) & 0x70);
        *(uint4*)(asm_ + AOFF_Q + sw) = *(const uint4*)(Q0 + row * 64 + c16 * 8);
    }

    int kmin = q0 - LW + 1; if (kmin < 0) kmin = 0;
    const int kt0 = kmin >> 6, kt1 = q0 >> 6;
    const int nt = kt1 - kt0 + 1;

    attn_issue_stage(sbase, 0, K0 + (size_t)(kt0<<6)*HD, V0 + (size_t)(kt0<<6)*HD,
                     am0 + (kt0<<6), tid);
    CP_COMMIT();
    if (nt > 1) {
        attn_issue_stage(sbase, 1, K0 + (size_t)((kt0+1)<<6)*HD, V0 + (size_t)((kt0+1)<<6)*HD,
                         am0 + ((kt0+1)<<6), tid);
        CP_COMMIT();
    }

    __syncthreads();

    uint32_t aq[4][4];
    #pragma unroll
    for (int kk = 0; kk < 4; kk++) {
        const int row = warp * 16 + (mId & 1) * 8 + rIn;
        const int colB = (kk * 16 + (mId >> 1) * 8) * 2;
        const uint32_t off = row * 128 + colB;
        const uint32_t sw = off ^ ((off >> 3) & 0x70);
        ldsm_x4(aq[kk][0], aq[kk][1], aq[kk][2], aq[kk][3], sbase + AOFF_Q + sw);
    }

    float o[8][4];
    #pragma unroll
    for (int j = 0; j < 8; j++)
        #pragma unroll
        for (int e = 0; e < 4; e++) o[j][e] = 0.f;
    float l0 = 0.f, l1 = 0.f;
    const int r0g = q0 + warp * 16 + g;
    const int r1g = r0g + 8;
    const int rowlow  = q0 + warp * 16;
    const int rowhigh = rowlow + 15;

    for (int i = 0; i < nt; i++) {
        const int kt = kt0 + i, buf = i & 1;
        const int k0 = kt << 6;
        if (i + 1 < nt) { CP_WAIT(1); } else { CP_WAIT(0); }
        __syncthreads();

        const uint32_t stg = sbase + AOFF_STG + buf * ASTG_STRIDE;
        const uint32_t sK = stg, sV = stg + 8192;
        const int* sAm = (const int*)(asm_ + AOFF_STG + buf * ASTG_STRIDE + 16384);

        float sc[8][4];
        #pragma unroll
        for (int j = 0; j < 8; j++)
            #pragma unroll
            for (int e = 0; e < 4; e++) sc[j][e] = 0.f;

        #pragma unroll
        for (int kk = 0; kk < 4; kk++) {
            uint32_t b[8][2];
            #pragma unroll
            for (int ntp = 0; ntp < 4; ntp++) {
                const int row = ntp * 16 + (mId >> 1) * 8 + rIn;
                const int colB = (kk * 16 + (mId & 1) * 8) * 2;
                const uint32_t off = row * 128 + colB;
                const uint32_t sw = off ^ ((off >> 3) & 0x70);
                ldsm_x4(b[2*ntp][0], b[2*ntp][1], b[2*ntp+1][0], b[2*ntp+1][1], sK + sw);
            }
            #pragma unroll
            for (int j = 0; j < 8; j++)
                mma_f16(sc[j], aq[kk], b[j]);
        }

        // Warp-uniform interior test: tile fully causal, fully in-window, and
        // amask all ones -> skip all per-element mask logic (values identical).
        const bool mask_ok = (sAm[lane] != 0) && (sAm[32 + lane] != 0);
        const bool fast = (k0 + 63 <= rowlow) && (rowhigh - k0 < LW) &&
                          __all_sync(0xffffffffu, mask_ok);

        if (fast) {
            #pragma unroll
            for (int j = 0; j < 8; j++) {
                const float p0 = ex2(sc[j][0] - SM_SHIFT);
                const float p1 = ex2(sc[j][1] - SM_SHIFT);
                const float p2 = ex2(sc[j][2] - SM_SHIFT);
                const float p3 = ex2(sc[j][3] - SM_SHIFT);
                sc[j][0] = p0; sc[j][1] = p1; sc[j][2] = p2; sc[j][3] = p3;
                l0 += p0 + p1; l1 += p2 + p3;
            }
        } else {
            #pragma unroll
            for (int j = 0; j < 8; j++) {
                const int ce = 8*j + 2*t, co = ce + 1;
                const int ae = sAm[ce], ao = sAm[co];
                const int gce = k0 + ce, gco = k0 + co;
                const bool a0 = ((unsigned)(r0g - gce) < (unsigned)LW) && (ae != 0);
                const bool a1 = ((unsigned)(r0g - gco) < (unsigned)LW) && (ao != 0);
                const bool a2 = ((unsigned)(r1g - gce) < (unsigned)LW) && (ae != 0);
                const bool a3 = ((unsigned)(r1g - gco) < (unsigned)LW) && (ao != 0);
                const float p0 = a0 ? ex2(sc[j][0] - SM_SHIFT) : 0.f;
                const float p1 = a1 ? ex2(sc[j][1] - SM_SHIFT) : 0.f;
                const float p2 = a2 ? ex2(sc[j][2] - SM_SHIFT) : 0.f;
                const float p3 = a3 ? ex2(sc[j][3] - SM_SHIFT) : 0.f;
                sc[j][0] = p0; sc[j][1] = p1; sc[j][2] = p2; sc[j][3] = p3;
                l0 += p0 + p1; l1 += p2 + p3;
            }
        }

        uint32_t pa[4][4];
        #pragma unroll
        for (int kb = 0; kb < 4; kb++) {
            const int j0 = 2*kb, j1 = 2*kb + 1;
            pa[kb][0] = pack_h2(sc[j0][0], sc[j0][1]);
            pa[kb][1] = pack_h2(sc[j0][2], sc[j0][3]);
            pa[kb][2] = pack_h2(sc[j1][0], sc[j1][1]);
            pa[kb][3] = pack_h2(sc[j1][2], sc[j1][3]);
        }

        #pragma unroll
        for (int kb = 0; kb < 4; kb++) {
            uint32_t v[8][2];
            #pragma unroll
            for (int dp = 0; dp < 4; dp++) {
                const int row = kb * 16 + (mId & 1) * 8 + rIn;
                const int colB = (dp * 16 + (mId >> 1) * 8) * 2;
                const uint32_t off = row * 128 + colB;
                const uint32_t sw = off ^ ((off >> 3) & 0x70);
                ldsm_x4_t(v[2*dp][0], v[2*dp][1], v[2*dp+1][0], v[2*dp+1][1], sV + sw);
            }
            #pragma unroll
            for (int j = 0; j < 8; j++)
                mma_f16(o[j], pa[kb], v[j]);
        }

        __syncthreads();
        if (i + 2 < nt) {
            const int kn = (kt + 2) << 6;
            attn_issue_stage(sbase, buf, K0 + (size_t)kn*HD, V0 + (size_t)kn*HD,
                             am0 + kn, tid);
            CP_COMMIT();
        }
    }

    l0 += __shfl_xor_sync(0xffffffffu, l0, 1);
    l0 += __shfl_xor_sync(0xffffffffu, l0, 2);
    l1 += __shfl_xor_sync(0xffffffffu, l1, 1);
    l1 += __shfl_xor_sync(0xffffffffu, l1, 2);

    const float inv0 = 1.0f / l0, inv1 = 1.0f / l1;
    const size_t tok0 = (size_t)(bz*S + r0g) * NE + h*HD;
    const size_t tok1 = (size_t)(bz*S + r1g) * NE + h*HD;
    #pragma unroll
    for (int j = 0; j < 8; j++) {
        const int d0 = 8*j + 2*t;
        *(uint32_t*)(g_y + tok0 + d0) = pack_h2(o[j][0]*inv0, o[j][1]*inv0);
        *(uint32_t*)(g_y + tok1 + d0) = pack_h2(o[j][2]*inv1, o[j][3]*inv1);
    }
}

// ---------------- launch ----------------------------------------------------
extern "C" void kernel_launch(void* const* d_in, const int* in_sizes, int n_in,
                              void* d_out, int out_size)
{
    const float* x     = (const float*)d_in[0];
    const float* ve    = (const float*)d_in[1];
    const float* cosb  = (const float*)d_in[2];
    const float* sinb  = (const float*)d_in[3];
    const float* Wq    = (const float*)d_in[4];
    const float* Wk    = (const float*)d_in[5];
    const float* Wv    = (const float*)d_in[6];
    const float* Wproj = (const float*)d_in[7];
    const float* Wgate = (const float*)d_in[8];
    const int*   amask = (const int*)d_in[9];
    const int*   lw    = (const int*)d_in[10];
    float* out = (float*)d_out;

    const int S = in_sizes[2] / 32;        // cos is (S,1,32)
    const int B = in_sizes[0] / (S * NE);
    const int M = B * S;

    __half *xp, *wp, *wpp, *yp;
    cudaGetSymbolAddress((void**)&xp,  g_x);
    cudaGetSymbolAddress((void**)&wp,  g_w);
    cudaGetSymbolAddress((void**)&wpp, g_wp);
    cudaGetSymbolAddress((void**)&yp,  g_y);

    // merged fp32 -> fp16 converts
    const int nx4 = M * NE / 4;
    const int ntot = nx4 + 655360;
    cvt_all<<<(ntot + 255)/256, 256>>>(x, Wq, Wk, Wv, Wproj, xp, nx4);

    cudaFuncSetAttribute(gemm_qkv, cudaFuncAttributeMaxDynamicSharedMemorySize, GSMEM);
    cudaFuncSetAttribute(gemm_mma, cudaFuncAttributeMaxDynamicSharedMemorySize, GSMEM);

    // fused QKV projection + rope/rmsnorm/gate epilogue (32x64 warp tile)
    gemm_qkv<<<dim3(12, M/128), 256, GSMEM>>>(xp, wp, x, ve, cosb, sinb, Wgate, S);

    // attention (tensor-core flash, fixed-shift softmax, fast interior path)
    cudaFuncSetAttribute(attn_kernel, cudaFuncAttributeMaxDynamicSharedMemorySize, ASMEM);
    attn_kernel<<<dim3(S/64, NH, B), 128, ASMEM>>>(amask, lw, S);

    // output projection (64x64 warp tile) straight into d_out
    gemm_mma<<<dim3(8, M/128), 128, GSMEM>>>(yp, wpp, out, 1024);
}